// round 13
// baseline (speedup 1.0000x reference)
#include <cuda_runtime.h>
#include <cuda_bf16.h>
#include <cstdint>

#define C_DIM 512
#define L_DIM 2048
#define BATCH 4
#define HEADS 8
#define HDIM 64
#define CL (C_DIM * L_DIM)

// ---------------------------------------------------------------------------
// Helpers
// ---------------------------------------------------------------------------
__device__ __forceinline__ uint32_t s2u(const void* p) {
    uint32_t a;
    asm("{ .reg .u64 t; cvta.to.shared.u64 t, %1; cvt.u32.u64 %0, t; }" : "=r"(a) : "l"(p));
    return a;
}
__device__ __forceinline__ void ldsm4(uint32_t* r, uint32_t a) {
    asm volatile("ldmatrix.sync.aligned.m8n8.x4.shared.b16 {%0,%1,%2,%3}, [%4];"
                 : "=r"(r[0]), "=r"(r[1]), "=r"(r[2]), "=r"(r[3]) : "r"(a));
}
__device__ __forceinline__ void ldsm4t(uint32_t* r, uint32_t a) {
    asm volatile("ldmatrix.sync.aligned.m8n8.x4.trans.shared.b16 {%0,%1,%2,%3}, [%4];"
                 : "=r"(r[0]), "=r"(r[1]), "=r"(r[2]), "=r"(r[3]) : "r"(a));
}
__device__ __forceinline__ void mma16816(float* c, const uint32_t* a, const uint32_t* b) {
    asm volatile("mma.sync.aligned.m16n8k16.row.col.f32.bf16.bf16.f32 "
                 "{%0,%1,%2,%3}, {%4,%5,%6,%7}, {%8,%9}, {%0,%1,%2,%3};"
                 : "+f"(c[0]), "+f"(c[1]), "+f"(c[2]), "+f"(c[3])
                 : "r"(a[0]), "r"(a[1]), "r"(a[2]), "r"(a[3]), "r"(b[0]), "r"(b[1]));
}
#define CP16(dst, src)  asm volatile("cp.async.cg.shared.global [%0], [%1], 16;" :: "r"(dst), "l"(src))
#define CPCOMMIT()      asm volatile("cp.async.commit_group;")
#define CPWAIT1()       asm volatile("cp.async.wait_group 1;" ::: "memory")
#define CPWAIT0()       asm volatile("cp.async.wait_group 0;" ::: "memory")
#define SW(x)  ((x) ^ (((x) >> 3) & 0x70))   // 128B-row swizzle
#define GSW(x) ((x) ^ (((x) >> 3) & 0x30))   // 64B-row swizzle
__device__ __forceinline__ void split_bf(float x, __nv_bfloat16& h, __nv_bfloat16& l) {
    h = __float2bfloat16(x);
    l = __float2bfloat16(x - __bfloat162float(h));
}
__device__ __forceinline__ uint32_t packb(__nv_bfloat16 a, __nv_bfloat16 b) {
    __nv_bfloat162 t(a, b);
    return *(uint32_t*)&t;
}
// exp2 via FFMA/ALU only (no MUFU). |y| <= 14.5 guaranteed by clip.
__device__ __forceinline__ float exp2_poly(float y) {
    float r = y + 12582912.f;
    int n = __float_as_int(r) - 0x4B400000;
    float f = y - (r - 12582912.f);
    float p = 0.0013333558f;
    p = p * f + 0.0096181291f;
    p = p * f + 0.0555041087f;
    p = p * f + 0.2402265069f;
    p = p * f + 0.6931471825f;
    p = p * f + 1.0f;
    return __int_as_float(__float_as_int(p) + (n << 23));
}

// ---------------------------------------------------------------------------
// Scratch
// ---------------------------------------------------------------------------
__device__ float g_z[BATCH * CL];
__device__ __nv_bfloat16 g_qkvh[BATCH * 3 * CL], g_qkvl[BATCH * 3 * CL];  // [b][3C][L]
__device__ __nv_bfloat16 g_xTh[BATCH * CL], g_xTl[BATCH * CL];            // x^T [b][l][c]
__device__ __nv_bfloat16 g_aTh[BATCH * CL], g_aTl[BATCH * CL];            // att^T [b][l][c]
__device__ __nv_bfloat16 g_wqh[3 * C_DIM * C_DIM], g_wql[3 * C_DIM * C_DIM];
__device__ __nv_bfloat16 g_wph[C_DIM * C_DIM], g_wpl[C_DIM * C_DIM];

// ---------------------------------------------------------------------------
// Elementwise fp32 -> bf16 hi/lo split
// ---------------------------------------------------------------------------
__global__ __launch_bounds__(256) void esplit_kernel(
    const float* __restrict__ s, __nv_bfloat16* __restrict__ dh,
    __nv_bfloat16* __restrict__ dl, int n4)
{
    int i = blockIdx.x * 256 + threadIdx.x;
    if (i >= n4) return;
    float4 v = ((const float4*)s)[i];
    __nv_bfloat16 h0, l0, h1, l1, h2, l2, h3, l3;
    split_bf(v.x, h0, l0); split_bf(v.y, h1, l1);
    split_bf(v.z, h2, l2); split_bf(v.w, h3, l3);
    uint2 wh = { packb(h0, h1), packb(h2, h3) };
    uint2 wl = { packb(l0, l1), packb(l2, l3) };
    ((uint2*)dh)[i] = wh;
    ((uint2*)dl)[i] = wl;
}

// ---------------------------------------------------------------------------
// Transpose + split x: fp32 [64r][128c of L] -> bf16 hi/lo [128 l][64 c]
// ---------------------------------------------------------------------------
__global__ __launch_bounds__(256) void tsplit_x_kernel(
    const float* __restrict__ x, __nv_bfloat16* __restrict__ dh, __nv_bfloat16* __restrict__ dl)
{
    __shared__ __nv_bfloat16 th[128 * 64], tl[128 * 64];
    const int lc = blockIdx.x, cc = blockIdx.y, b = blockIdx.z;
    const float* src = x + ((size_t)b * C_DIM + cc * 64) * L_DIM + lc * 128;
    size_t doff = ((size_t)b * L_DIM + lc * 128) * C_DIM + cc * 64;
    __nv_bfloat16* dhp = dh + doff;
    __nv_bfloat16* dlp = dl + doff;
    const int t = threadIdx.x;
    {
        int r = t >> 2, cb = (t & 3) * 32;
        const float4* s4 = (const float4*)(src + (size_t)r * L_DIM + cb);
        #pragma unroll
        for (int u = 0; u < 8; u++) {
            float4 v = s4[u];
            float vv[4] = {v.x, v.y, v.z, v.w};
            #pragma unroll
            for (int e = 0; e < 4; e++) {
                int c = cb + 4 * u + e;
                __nv_bfloat16 hb, lb; split_bf(vv[e], hb, lb);
                th[c * 64 + r] = hb;
                tl[c * 64 + r] = lb;
            }
        }
    }
    __syncthreads();
    {
        int l = t >> 1, eo = (t & 1) * 32;
        #pragma unroll
        for (int u = 0; u < 4; u++) {
            *(uint4*)(dhp + (size_t)l * C_DIM + eo + 8 * u) = *(uint4*)&th[l * 64 + eo + 8 * u];
            *(uint4*)(dlp + (size_t)l * C_DIM + eo + 8 * u) = *(uint4*)&tl[l * 64 + eo + 8 * u];
        }
    }
}

// ---------------------------------------------------------------------------
// Tensor-core GEMM, cp.async 3-stage. C = A[MxK]*B[b][NxK] + bias.
// OUTBF: write clipped bf16 hi/lo to obh/obl instead of fp32 Cmat.
// ---------------------------------------------------------------------------
#define GSTG 49152
#define GOFF_AL 8192
#define GOFF_BH 16384
#define GOFF_BL 32768
#define GEMM_SMEM (3 * GSTG)

template<bool CLIP, bool RES, bool OUTBF>
__global__ __launch_bounds__(256) void mma_gemm_kernel(
    const __nv_bfloat16* __restrict__ Ah, const __nv_bfloat16* __restrict__ Al,
    const __nv_bfloat16* __restrict__ Bh, const __nv_bfloat16* __restrict__ Bl,
    float* __restrict__ Cmat, __nv_bfloat16* __restrict__ obh, __nv_bfloat16* __restrict__ obl,
    const float* __restrict__ bias, const float* __restrict__ res,
    int N, int K, size_t strideB, size_t strideC, size_t strideR)
{
    extern __shared__ char gsm[];
    const uint32_t sb = s2u(gsm);

    const int t = threadIdx.x;
    const int warp = t >> 5, lane = t & 31;
    const int wm = warp & 1, wn = warp >> 1;
    const int m0w = wm * 64, n0w = wn * 64;
    const int n0 = blockIdx.x * 256, m0 = blockIdx.y * 128;

    const int ar = t >> 1, aco = (t & 1) * 32;
    const int br = t;
    const char* pAh = (const char*)(Ah + (size_t)(m0 + ar) * K) + aco;
    const char* pAl = (const char*)(Al + (size_t)(m0 + ar) * K) + aco;
    const char* pBh = (const char*)(Bh + strideB * blockIdx.z + (size_t)(n0 + br) * K);
    const char* pBl = (const char*)(Bl + strideB * blockIdx.z + (size_t)(n0 + br) * K);
    const uint32_t dA0 = GSW(ar * 64 + aco), dA1 = GSW(ar * 64 + aco + 16);
    uint32_t dB[4];
    #pragma unroll
    for (int u = 0; u < 4; u++) dB[u] = GSW(br * 64 + u * 16);

    const int brow = (lane & 7) + ((lane >> 4) << 3);
    const int bcol = ((lane >> 3) & 1) * 16;

    const int NCH = K >> 5;

    #pragma unroll
    for (int c = 0; c < 2; c++) {
        uint32_t base = sb + c * GSTG;
        size_t go = (size_t)c * 64;
        CP16(base + dA0, pAh + go); CP16(base + dA1, pAh + go + 16);
        CP16(base + GOFF_AL + dA0, pAl + go); CP16(base + GOFF_AL + dA1, pAl + go + 16);
        #pragma unroll
        for (int u = 0; u < 4; u++) {
            CP16(base + GOFF_BH + dB[u], pBh + go + u * 16);
            CP16(base + GOFF_BL + dB[u], pBl + go + u * 16);
        }
        CPCOMMIT();
    }

    float acc[4][8][4] = {};
    int stg = 0, nstg = 2;

    for (int c = 0; c < NCH; c++) {
        CPWAIT1();
        __syncthreads();

        if (c + 2 < NCH) {
            uint32_t base = sb + nstg * GSTG;
            size_t go = (size_t)(c + 2) * 64;
            CP16(base + dA0, pAh + go); CP16(base + dA1, pAh + go + 16);
            CP16(base + GOFF_AL + dA0, pAl + go); CP16(base + GOFF_AL + dA1, pAl + go + 16);
            #pragma unroll
            for (int u = 0; u < 4; u++) {
                CP16(base + GOFF_BH + dB[u], pBh + go + u * 16);
                CP16(base + GOFF_BL + dB[u], pBl + go + u * 16);
            }
            CPCOMMIT();
        }
        nstg = nstg == 2 ? 0 : nstg + 1;

        const uint32_t sA = sb + stg * GSTG;
        #pragma unroll
        for (int kt = 0; kt < 2; kt++) {
            uint32_t ah[4][4], al[4][4];
            #pragma unroll
            for (int mi = 0; mi < 4; mi++) {
                uint32_t off = GSW((m0w + mi * 16 + (lane & 15)) * 64 + kt * 32 + (lane >> 4) * 16);
                ldsm4(ah[mi], sA + off);
                ldsm4(al[mi], sA + GOFF_AL + off);
            }
            #pragma unroll
            for (int nb = 0; nb < 4; nb++) {
                uint32_t bh[4], bl[4];
                uint32_t off = GSW((n0w + nb * 16 + brow) * 64 + kt * 32 + bcol);
                ldsm4(bh, sA + GOFF_BH + off);
                ldsm4(bl, sA + GOFF_BL + off);
                #pragma unroll
                for (int mi = 0; mi < 4; mi++) {
                    mma16816(acc[mi][2 * nb],     ah[mi], bh);
                    mma16816(acc[mi][2 * nb + 1], ah[mi], bh + 2);
                    mma16816(acc[mi][2 * nb],     ah[mi], bl);
                    mma16816(acc[mi][2 * nb + 1], ah[mi], bl + 2);
                    mma16816(acc[mi][2 * nb],     al[mi], bh);
                    mma16816(acc[mi][2 * nb + 1], al[mi], bh + 2);
                }
            }
        }
        stg = stg == 2 ? 0 : stg + 1;
    }

    // ---- epilogue
    float* Cp = OUTBF ? nullptr : (Cmat + strideC * blockIdx.z);
    __nv_bfloat16* oh = OUTBF ? (obh + strideC * blockIdx.z) : nullptr;
    __nv_bfloat16* ol = OUTBF ? (obl + strideC * blockIdx.z) : nullptr;
    const float* Rp = RES ? (res + strideR * blockIdx.z) : nullptr;
    #pragma unroll
    for (int mi = 0; mi < 4; mi++) {
        int r0 = m0 + m0w + mi * 16 + (lane >> 2);
        float b0 = bias[r0], b1 = bias[r0 + 8];
        #pragma unroll
        for (int nb = 0; nb < 8; nb++) {
            int col = n0 + n0w + nb * 8 + (lane & 3) * 2;
            float2 v0 = { acc[mi][nb][0] + b0, acc[mi][nb][1] + b0 };
            float2 v1 = { acc[mi][nb][2] + b1, acc[mi][nb][3] + b1 };
            if (CLIP) {
                v0.x = fminf(10.f, fmaxf(-10.f, v0.x));
                v0.y = fminf(10.f, fmaxf(-10.f, v0.y));
                v1.x = fminf(10.f, fmaxf(-10.f, v1.x));
                v1.y = fminf(10.f, fmaxf(-10.f, v1.y));
            }
            if (RES) {
                float2 r0v = *(const float2*)(Rp + (size_t)r0 * N + col);
                float2 r1v = *(const float2*)(Rp + (size_t)(r0 + 8) * N + col);
                v0.x += r0v.x; v0.y += r0v.y;
                v1.x += r1v.x; v1.y += r1v.y;
            }
            if (OUTBF) {
                __nv_bfloat16 h0, l0, h1, l1;
                split_bf(v0.x, h0, l0); split_bf(v0.y, h1, l1);
                *(uint32_t*)(oh + (size_t)r0 * N + col) = packb(h0, h1);
                *(uint32_t*)(ol + (size_t)r0 * N + col) = packb(l0, l1);
                split_bf(v1.x, h0, l0); split_bf(v1.y, h1, l1);
                *(uint32_t*)(oh + (size_t)(r0 + 8) * N + col) = packb(h0, h1);
                *(uint32_t*)(ol + (size_t)(r0 + 8) * N + col) = packb(l0, l1);
            } else {
                *(float2*)(Cp + (size_t)r0 * N + col) = v0;
                *(float2*)(Cp + (size_t)(r0 + 8) * N + col) = v1;
            }
        }
    }
}

// ---------------------------------------------------------------------------
// Flash attention: 128 threads, 64 queries/CTA (2 CTAs/SM for overlap).
// Q/K fragments via ldmatrix.trans straight from d-major bf16 qkv.
// smem: 3 stages x 32KB (stage = KHI 8|KLO 8|VHI 8|VLO 8). Q staged in stage0.
// ---------------------------------------------------------------------------
#define KVSTG 32768
#define OFF_KL 8192
#define OFF_VH 16384
#define OFF_VL 24576
#define ATTN_SMEM (3 * KVSTG)

__global__ __launch_bounds__(128) void attn_mma_kernel(
    const __nv_bfloat16* __restrict__ qkvh, const __nv_bfloat16* __restrict__ qkvl,
    __nv_bfloat16* __restrict__ aTh, __nv_bfloat16* __restrict__ aTl)
{
    extern __shared__ char sm[];
    const uint32_t sb = s2u(sm);
    const int tid = threadIdx.x;
    const int w = tid >> 5, lane = tid & 31;
    const int b = blockIdx.z, h = blockIdx.y;
    const int i0 = blockIdx.x * 64;

    const size_t bbase = (size_t)b * 3 * C_DIM;

    // ---- stage Q (hi at stage0+0, lo at stage0+OFF_KL), rows = d, 128B rows
    {
        const int qr = tid >> 1, qc = (tid & 1) * 32;   // d row, i elem offset
        const char* sqh = (const char*)(qkvh + (bbase + h * 64 + qr) * L_DIM + i0 + qc);
        const char* sql = (const char*)(qkvl + (bbase + h * 64 + qr) * L_DIM + i0 + qc);
        #pragma unroll
        for (int u = 0; u < 4; u++) {
            uint32_t d = SW(qr * 128 + qc * 2 + u * 16);
            CP16(sb + d, sqh + u * 16);
            CP16(sb + OFF_KL + d, sql + u * 16);
        }
        CPCOMMIT();
    }
    CPWAIT0();
    __syncthreads();

    // ---- Q a-fragments via trans-ldsm: tiles a0..a3 = (i0:8,d0:8),(i8:16,d0:8),(i0:8,d8:16),(i8:16,d8:16)
    uint32_t qh[4][4], ql[4][4];
    {
        const int rd = ((lane >> 4) << 3) + (lane & 7);          // d within 16
        const int ci = (w << 4) + (((lane >> 3) & 1) << 3);      // i col
        #pragma unroll
        for (int dt = 0; dt < 4; dt++) {
            uint32_t off = SW((dt * 16 + rd) * 128 + ci * 2);
            ldsm4t(qh[dt], sb + off);
            ldsm4t(ql[dt], sb + OFF_KL + off);
        }
    }
    __syncthreads();   // stage0 free for KV pipeline

    // ---- KV loader mapping (rows = d, 128B rows of 64 j)
    const int kr = tid >> 1, kc = (tid & 1) * 32;
    const char* pKh = (const char*)(qkvh + (bbase + C_DIM + h * 64 + kr) * L_DIM + kc);
    const char* pKl = (const char*)(qkvl + (bbase + C_DIM + h * 64 + kr) * L_DIM + kc);
    const char* pVh = (const char*)(qkvh + (bbase + 2 * C_DIM + h * 64 + kr) * L_DIM + kc);
    const char* pVl = (const char*)(qkvl + (bbase + 2 * C_DIM + h * 64 + kr) * L_DIM + kc);
    uint32_t dK[4];
    #pragma unroll
    for (int u = 0; u < 4; u++) dK[u] = SW(kr * 128 + kc * 2 + u * 16);

    #pragma unroll
    for (int tt = 0; tt < 2; tt++) {
        uint32_t base = sb + tt * KVSTG;
        size_t go = (size_t)tt * 128;   // 64 j elems = 128B
        #pragma unroll
        for (int u = 0; u < 4; u++) {
            CP16(base + dK[u], pKh + go + u * 16);
            CP16(base + OFF_KL + dK[u], pKl + go + u * 16);
            CP16(base + OFF_VH + dK[u], pVh + go + u * 16);
            CP16(base + OFF_VL + dK[u], pVl + go + u * 16);
        }
        CPCOMMIT();
    }

    // fragment lane addressing
    const int krd = (((lane >> 3) & 1) << 3) + (lane & 7);   // K trans: d part
    const int kcj = (lane >> 4) << 3;                        // K trans: j part
    const int brow = (lane & 7) + ((lane >> 4) << 3);        // V non-trans
    const int bcol = ((lane >> 3) & 1) * 16;

    const float K1 = 0.125f * 1.44269504f;
    const float LIM = 10.0f * 1.44269504f;

    float oc[8][4] = {};
    float racc0 = 0.f, racc1 = 0.f;
    int stg = 0, nstg = 2;

    for (int t = 0; t < 32; t++) {
        CPWAIT1();
        __syncthreads();

        if (t + 2 < 32) {
            uint32_t base = sb + nstg * KVSTG;
            size_t go = (size_t)(t + 2) * 128;
            #pragma unroll
            for (int u = 0; u < 4; u++) {
                CP16(base + dK[u], pKh + go + u * 16);
                CP16(base + OFF_KL + dK[u], pKl + go + u * 16);
                CP16(base + OFF_VH + dK[u], pVh + go + u * 16);
                CP16(base + OFF_VL + dK[u], pVl + go + u * 16);
            }
            CPCOMMIT();
        }
        nstg = nstg == 2 ? 0 : nstg + 1;

        const uint32_t sKV = sb + stg * KVSTG;

        // ---- S = Q K^T  (K via trans-ldsm from [d][j])
        float sc[8][4] = {};
        #pragma unroll
        for (int dt = 0; dt < 4; dt++) {
            #pragma unroll
            for (int jb = 0; jb < 4; jb++) {
                uint32_t kh[4], kl[4];
                uint32_t off = SW((dt * 16 + krd) * 128 + (jb * 16 + kcj) * 2);
                ldsm4t(kh, sKV + off);
                ldsm4t(kl, sKV + OFF_KL + off);
                mma16816(sc[2 * jb],     qh[dt], kh);
                mma16816(sc[2 * jb + 1], qh[dt], kh + 2);
                mma16816(sc[2 * jb],     qh[dt], kl);
                mma16816(sc[2 * jb + 1], qh[dt], kl + 2);
                mma16816(sc[2 * jb],     ql[dt], kh);
                mma16816(sc[2 * jb + 1], ql[dt], kh + 2);
            }
        }

        // ---- softmax numerator
        #pragma unroll
        for (int nt = 0; nt < 8; nt++) {
            #pragma unroll
            for (int k = 0; k < 4; k++) {
                float y = sc[nt][k] * K1;
                y = fminf(LIM, fmaxf(-LIM, y));
                float p = exp2_poly(y);
                sc[nt][k] = p;
                if (k < 2) racc0 += p; else racc1 += p;
            }
        }

        // ---- pack P fragments from registers
        uint32_t ph[4][4], pl[4][4];
        #pragma unroll
        for (int q = 0; q < 4; q++) {
            __nv_bfloat16 h0, l0, h1, l1;
            split_bf(sc[2 * q][0], h0, l0); split_bf(sc[2 * q][1], h1, l1);
            ph[q][0] = packb(h0, h1); pl[q][0] = packb(l0, l1);
            split_bf(sc[2 * q][2], h0, l0); split_bf(sc[2 * q][3], h1, l1);
            ph[q][1] = packb(h0, h1); pl[q][1] = packb(l0, l1);
            split_bf(sc[2 * q + 1][0], h0, l0); split_bf(sc[2 * q + 1][1], h1, l1);
            ph[q][2] = packb(h0, h1); pl[q][2] = packb(l0, l1);
            split_bf(sc[2 * q + 1][2], h0, l0); split_bf(sc[2 * q + 1][3], h1, l1);
            ph[q][3] = packb(h0, h1); pl[q][3] = packb(l0, l1);
        }

        // ---- O += P V^T  (V non-trans from [d][j])
        #pragma unroll
        for (int kt = 0; kt < 4; kt++) {
            #pragma unroll
            for (int db = 0; db < 4; db++) {
                uint32_t vvh[4], vvl[4];
                uint32_t off = SW((db * 16 + brow) * 128 + kt * 32 + bcol);
                ldsm4(vvh, sKV + OFF_VH + off);
                ldsm4(vvl, sKV + OFF_VL + off);
                mma16816(oc[2 * db],     ph[kt], vvh);
                mma16816(oc[2 * db + 1], ph[kt], vvh + 2);
                mma16816(oc[2 * db],     ph[kt], vvl);
                mma16816(oc[2 * db + 1], ph[kt], vvl + 2);
                mma16816(oc[2 * db],     pl[kt], vvh);
                mma16816(oc[2 * db + 1], pl[kt], vvh + 2);
            }
        }
        stg = stg == 2 ? 0 : stg + 1;
    }

    // ---- row denominators (quad reduce)
    racc0 += __shfl_xor_sync(0xffffffffu, racc0, 1);
    racc0 += __shfl_xor_sync(0xffffffffu, racc0, 2);
    racc1 += __shfl_xor_sync(0xffffffffu, racc1, 1);
    racc1 += __shfl_xor_sync(0xffffffffu, racc1, 2);
    const float inv0 = 1.0f / racc0;
    const float inv1 = 1.0f / racc1;

    // ---- write att^T hi/lo bf16: [b][l][c], c = h*64 + d
    const int ibase = i0 + w * 16 + (lane >> 2);
    const size_t rowbase = ((size_t)b * L_DIM + ibase) * C_DIM + h * 64;
    #pragma unroll
    for (int nt = 0; nt < 8; nt++) {
        int d = nt * 8 + 2 * (lane & 3);
        float a0 = oc[nt][0] * inv0, a1 = oc[nt][1] * inv0;
        float a2 = oc[nt][2] * inv1, a3 = oc[nt][3] * inv1;
        __nv_bfloat16 h0, l0, h1, l1;
        split_bf(a0, h0, l0); split_bf(a1, h1, l1);
        *(uint32_t*)(aTh + rowbase + d) = packb(h0, h1);
        *(uint32_t*)(aTl + rowbase + d) = packb(l0, l1);
        split_bf(a2, h0, l0); split_bf(a3, h1, l1);
        *(uint32_t*)(aTh + rowbase + (size_t)8 * C_DIM + d) = packb(h0, h1);
        *(uint32_t*)(aTl + rowbase + (size_t)8 * C_DIM + d) = packb(l0, l1);
    }
}

// ---------------------------------------------------------------------------
// GroupNorm (proven)
// ---------------------------------------------------------------------------
__global__ __launch_bounds__(256) void gn_kernel(
    const float* __restrict__ z, const float* __restrict__ gamma,
    const float* __restrict__ beta, float* __restrict__ outp)
{
    const int bg = blockIdx.x;
    const int b = bg >> 5, g = bg & 31;
    const float* zp = z + ((size_t)b * C_DIM + g * 16) * L_DIM;
    float* op = outp + ((size_t)b * C_DIM + g * 16) * L_DIM;
    const int t = threadIdx.x;

    float s = 0.f, ss = 0.f;
    const float4* z4 = (const float4*)zp;
    for (int i = t; i < 8192; i += 256) {
        float4 v = z4[i];
        s  += v.x + v.y + v.z + v.w;
        ss += v.x * v.x + v.y * v.y + v.z * v.z + v.w * v.w;
    }
    __shared__ float rs[8], rss[8];
    __shared__ float smu, srstd;
    #pragma unroll
    for (int o = 16; o; o >>= 1) {
        s  += __shfl_xor_sync(0xffffffffu, s, o);
        ss += __shfl_xor_sync(0xffffffffu, ss, o);
    }
    if ((t & 31) == 0) { rs[t >> 5] = s; rss[t >> 5] = ss; }
    __syncthreads();
    if (t == 0) {
        float ts = 0.f, tss = 0.f;
        #pragma unroll
        for (int wv = 0; wv < 8; wv++) { ts += rs[wv]; tss += rss[wv]; }
        float mu = ts * (1.f / 32768.f);
        float var = tss * (1.f / 32768.f) - mu * mu;
        smu = mu;
        srstd = rsqrtf(var + 1e-5f);
    }
    __syncthreads();
    const float mu = smu, rstd = srstd;
    float4* o4 = (float4*)op;
    for (int i = t; i < 8192; i += 256) {
        int ch = g * 16 + (i >> 9);
        float ga = gamma[ch] * rstd;
        float be = beta[ch];
        float4 v = z4[i];
        v.x = (v.x - mu) * ga + be;
        v.y = (v.y - mu) * ga + be;
        v.z = (v.z - mu) * ga + be;
        v.w = (v.w - mu) * ga + be;
        o4[i] = v;
    }
}

// ---------------------------------------------------------------------------
extern "C" void kernel_launch(void* const* d_in, const int* in_sizes, int n_in,
                              void* d_out, int out_size)
{
    const float* x     = (const float*)d_in[0];
    const float* Wqkv  = (const float*)d_in[1];
    const float* bqkv  = (const float*)d_in[2];
    const float* Wproj = (const float*)d_in[3];
    const float* bproj = (const float*)d_in[4];
    const float* gamma = (const float*)d_in[5];
    const float* beta  = (const float*)d_in[6];
    float* out = (float*)d_out;

    float* zbuf;
    __nv_bfloat16 *qkvh, *qkvl, *xTh, *xTl, *aTh, *aTl, *wqh, *wql, *wph, *wpl;
    cudaGetSymbolAddress((void**)&zbuf, g_z);
    cudaGetSymbolAddress((void**)&qkvh, g_qkvh);
    cudaGetSymbolAddress((void**)&qkvl, g_qkvl);
    cudaGetSymbolAddress((void**)&xTh,  g_xTh);
    cudaGetSymbolAddress((void**)&xTl,  g_xTl);
    cudaGetSymbolAddress((void**)&aTh,  g_aTh);
    cudaGetSymbolAddress((void**)&aTl,  g_aTl);
    cudaGetSymbolAddress((void**)&wqh,  g_wqh);
    cudaGetSymbolAddress((void**)&wql,  g_wql);
    cudaGetSymbolAddress((void**)&wph,  g_wph);
    cudaGetSymbolAddress((void**)&wpl,  g_wpl);

    cudaFuncSetAttribute(attn_mma_kernel, cudaFuncAttributeMaxDynamicSharedMemorySize, ATTN_SMEM);
    cudaFuncSetAttribute(mma_gemm_kernel<true, false, true>,  cudaFuncAttributeMaxDynamicSharedMemorySize, GEMM_SMEM);
    cudaFuncSetAttribute(mma_gemm_kernel<false, true, false>, cudaFuncAttributeMaxDynamicSharedMemorySize, GEMM_SMEM);

    // pre-split inputs
    tsplit_x_kernel<<<dim3(16, 8, BATCH), 256>>>(x, xTh, xTl);
    esplit_kernel<<<(3 * C_DIM * C_DIM / 4 + 255) / 256, 256>>>(Wqkv, wqh, wql, 3 * C_DIM * C_DIM / 4);
    esplit_kernel<<<(C_DIM * C_DIM / 4 + 255) / 256, 256>>>(Wproj, wph, wpl, C_DIM * C_DIM / 4);

    // qkv = clip(Wqkv @ x + bqkv) -> bf16 hi/lo [b][3C][L]
    mma_gemm_kernel<true, false, true><<<dim3(8, 12, BATCH), 256, GEMM_SMEM>>>(
        wqh, wql, xTh, xTl, nullptr, qkvh, qkvl, bqkv, nullptr,
        L_DIM, C_DIM, (size_t)CL, (size_t)3 * CL, 0);

    // attention -> att^T hi/lo bf16
    attn_mma_kernel<<<dim3(32, HEADS, BATCH), 128, ATTN_SMEM>>>(qkvh, qkvl, aTh, aTl);

    // z = Wproj @ att + bproj + x
    mma_gemm_kernel<false, true, false><<<dim3(8, 4, BATCH), 256, GEMM_SMEM>>>(
        wph, wpl, aTh, aTl, zbuf, nullptr, nullptr, bproj, x,
        L_DIM, C_DIM, (size_t)CL, (size_t)CL, (size_t)CL);

    // out = groupnorm(z)
    gn_kernel<<<dim3(BATCH * 32), 256>>>(zbuf, gamma, beta, out);
}

// round 15
// speedup vs baseline: 1.0557x; 1.0557x over previous
#include <cuda_runtime.h>
#include <cuda_bf16.h>
#include <cstdint>

#define C_DIM 512
#define L_DIM 2048
#define BATCH 4
#define HEADS 8
#define HDIM 64
#define CL (C_DIM * L_DIM)

// ---------------------------------------------------------------------------
// Helpers
// ---------------------------------------------------------------------------
__device__ __forceinline__ uint32_t s2u(const void* p) {
    uint32_t a;
    asm("{ .reg .u64 t; cvta.to.shared.u64 t, %1; cvt.u32.u64 %0, t; }" : "=r"(a) : "l"(p));
    return a;
}
__device__ __forceinline__ void ldsm4(uint32_t* r, uint32_t a) {
    asm volatile("ldmatrix.sync.aligned.m8n8.x4.shared.b16 {%0,%1,%2,%3}, [%4];"
                 : "=r"(r[0]), "=r"(r[1]), "=r"(r[2]), "=r"(r[3]) : "r"(a));
}
__device__ __forceinline__ void ldsm4t(uint32_t* r, uint32_t a) {
    asm volatile("ldmatrix.sync.aligned.m8n8.x4.trans.shared.b16 {%0,%1,%2,%3}, [%4];"
                 : "=r"(r[0]), "=r"(r[1]), "=r"(r[2]), "=r"(r[3]) : "r"(a));
}
__device__ __forceinline__ void mma16816(float* c, const uint32_t* a, const uint32_t* b) {
    asm volatile("mma.sync.aligned.m16n8k16.row.col.f32.bf16.bf16.f32 "
                 "{%0,%1,%2,%3}, {%4,%5,%6,%7}, {%8,%9}, {%0,%1,%2,%3};"
                 : "+f"(c[0]), "+f"(c[1]), "+f"(c[2]), "+f"(c[3])
                 : "r"(a[0]), "r"(a[1]), "r"(a[2]), "r"(a[3]), "r"(b[0]), "r"(b[1]));
}
#define CP16(dst, src)  asm volatile("cp.async.cg.shared.global [%0], [%1], 16;" :: "r"(dst), "l"(src))
#define CPCOMMIT()      asm volatile("cp.async.commit_group;")
#define CPWAIT1()       asm volatile("cp.async.wait_group 1;" ::: "memory")
#define CPWAIT0()       asm volatile("cp.async.wait_group 0;" ::: "memory")
#define SW(x)  ((x) ^ (((x) >> 3) & 0x70))
#define GSW(x) ((x) ^ (((x) >> 3) & 0x30))
__device__ __forceinline__ void split_bf(float x, __nv_bfloat16& h, __nv_bfloat16& l) {
    h = __float2bfloat16(x);
    l = __float2bfloat16(x - __bfloat162float(h));
}
__device__ __forceinline__ uint32_t packb(__nv_bfloat16 a, __nv_bfloat16 b) {
    __nv_bfloat162 t(a, b);
    return *(uint32_t*)&t;
}
// exp2 via FFMA/ALU only (no MUFU). |y| <= 14.5 guaranteed by clip.
__device__ __forceinline__ float exp2_poly(float y) {
    float r = y + 12582912.f;
    int n = __float_as_int(r) - 0x4B400000;
    float f = y - (r - 12582912.f);
    float p = 0.0013333558f;
    p = p * f + 0.0096181291f;
    p = p * f + 0.0555041087f;
    p = p * f + 0.2402265069f;
    p = p * f + 0.6931471825f;
    p = p * f + 1.0f;
    return __int_as_float(__float_as_int(p) + (n << 23));
}

// ---------------------------------------------------------------------------
// Scratch
// ---------------------------------------------------------------------------
__device__ float g_z[BATCH * CL];
__device__ __nv_bfloat16 g_qkvh[BATCH * 3 * CL], g_qkvl[BATCH * 3 * CL];  // [b][3C][L]
__device__ __nv_bfloat16 g_xTh[BATCH * CL], g_xTl[BATCH * CL];            // x^T [b][l][c]
__device__ __nv_bfloat16 g_aTh[BATCH * CL], g_aTl[BATCH * CL];            // att^T [b][l][c]
__device__ __nv_bfloat16 g_wqh[3 * C_DIM * C_DIM], g_wql[3 * C_DIM * C_DIM];
__device__ __nv_bfloat16 g_wph[C_DIM * C_DIM], g_wpl[C_DIM * C_DIM];

// ---------------------------------------------------------------------------
// Elementwise fp32 -> bf16 hi/lo split
// ---------------------------------------------------------------------------
__global__ __launch_bounds__(256) void esplit_kernel(
    const float* __restrict__ s, __nv_bfloat16* __restrict__ dh,
    __nv_bfloat16* __restrict__ dl, int n4)
{
    int i = blockIdx.x * 256 + threadIdx.x;
    if (i >= n4) return;
    float4 v = ((const float4*)s)[i];
    __nv_bfloat16 h0, l0, h1, l1, h2, l2, h3, l3;
    split_bf(v.x, h0, l0); split_bf(v.y, h1, l1);
    split_bf(v.z, h2, l2); split_bf(v.w, h3, l3);
    uint2 wh = { packb(h0, h1), packb(h2, h3) };
    uint2 wl = { packb(l0, l1), packb(l2, l3) };
    ((uint2*)dh)[i] = wh;
    ((uint2*)dl)[i] = wl;
}

// ---------------------------------------------------------------------------
// Transpose + split x: fp32 [64r][128c of L] -> bf16 hi/lo [128 l][64 c]
// ---------------------------------------------------------------------------
__global__ __launch_bounds__(256) void tsplit_x_kernel(
    const float* __restrict__ x, __nv_bfloat16* __restrict__ dh, __nv_bfloat16* __restrict__ dl)
{
    __shared__ __nv_bfloat16 th[128 * 64], tl[128 * 64];
    const int lc = blockIdx.x, cc = blockIdx.y, b = blockIdx.z;
    const float* src = x + ((size_t)b * C_DIM + cc * 64) * L_DIM + lc * 128;
    size_t doff = ((size_t)b * L_DIM + lc * 128) * C_DIM + cc * 64;
    __nv_bfloat16* dhp = dh + doff;
    __nv_bfloat16* dlp = dl + doff;
    const int t = threadIdx.x;
    {
        int r = t >> 2, cb = (t & 3) * 32;
        const float4* s4 = (const float4*)(src + (size_t)r * L_DIM + cb);
        #pragma unroll
        for (int u = 0; u < 8; u++) {
            float4 v = s4[u];
            float vv[4] = {v.x, v.y, v.z, v.w};
            #pragma unroll
            for (int e = 0; e < 4; e++) {
                int c = cb + 4 * u + e;
                __nv_bfloat16 hb, lb; split_bf(vv[e], hb, lb);
                th[c * 64 + r] = hb;
                tl[c * 64 + r] = lb;
            }
        }
    }
    __syncthreads();
    {
        int l = t >> 1, eo = (t & 1) * 32;
        #pragma unroll
        for (int u = 0; u < 4; u++) {
            *(uint4*)(dhp + (size_t)l * C_DIM + eo + 8 * u) = *(uint4*)&th[l * 64 + eo + 8 * u];
            *(uint4*)(dlp + (size_t)l * C_DIM + eo + 8 * u) = *(uint4*)&tl[l * 64 + eo + 8 * u];
        }
    }
}

// ---------------------------------------------------------------------------
// Tensor-core GEMM, cp.async 3-stage, term-major MMA order (acc distance 8).
// ---------------------------------------------------------------------------
#define GSTG 49152
#define GOFF_AL 8192
#define GOFF_BH 16384
#define GOFF_BL 32768
#define GEMM_SMEM (3 * GSTG)

template<bool CLIP, bool RES, bool OUTBF>
__global__ __launch_bounds__(256) void mma_gemm_kernel(
    const __nv_bfloat16* __restrict__ Ah, const __nv_bfloat16* __restrict__ Al,
    const __nv_bfloat16* __restrict__ Bh, const __nv_bfloat16* __restrict__ Bl,
    float* __restrict__ Cmat, __nv_bfloat16* __restrict__ obh, __nv_bfloat16* __restrict__ obl,
    const float* __restrict__ bias, const float* __restrict__ res,
    int N, int K, size_t strideB, size_t strideC, size_t strideR)
{
    extern __shared__ char gsm[];
    const uint32_t sb = s2u(gsm);

    const int t = threadIdx.x;
    const int warp = t >> 5, lane = t & 31;
    const int wm = warp & 1, wn = warp >> 1;
    const int m0w = wm * 64, n0w = wn * 64;
    const int n0 = blockIdx.x * 256, m0 = blockIdx.y * 128;

    const int ar = t >> 1, aco = (t & 1) * 32;
    const int br = t;
    const char* pAh = (const char*)(Ah + (size_t)(m0 + ar) * K) + aco;
    const char* pAl = (const char*)(Al + (size_t)(m0 + ar) * K) + aco;
    const char* pBh = (const char*)(Bh + strideB * blockIdx.z + (size_t)(n0 + br) * K);
    const char* pBl = (const char*)(Bl + strideB * blockIdx.z + (size_t)(n0 + br) * K);
    const uint32_t dA0 = GSW(ar * 64 + aco), dA1 = GSW(ar * 64 + aco + 16);
    uint32_t dB[4];
    #pragma unroll
    for (int u = 0; u < 4; u++) dB[u] = GSW(br * 64 + u * 16);

    const int brow = (lane & 7) + ((lane >> 4) << 3);
    const int bcol = ((lane >> 3) & 1) * 16;

    const int NCH = K >> 5;

    #pragma unroll
    for (int c = 0; c < 2; c++) {
        uint32_t base = sb + c * GSTG;
        size_t go = (size_t)c * 64;
        CP16(base + dA0, pAh + go); CP16(base + dA1, pAh + go + 16);
        CP16(base + GOFF_AL + dA0, pAl + go); CP16(base + GOFF_AL + dA1, pAl + go + 16);
        #pragma unroll
        for (int u = 0; u < 4; u++) {
            CP16(base + GOFF_BH + dB[u], pBh + go + u * 16);
            CP16(base + GOFF_BL + dB[u], pBl + go + u * 16);
        }
        CPCOMMIT();
    }

    float acc[4][8][4] = {};
    int stg = 0, nstg = 2;

    for (int c = 0; c < NCH; c++) {
        CPWAIT1();
        __syncthreads();

        if (c + 2 < NCH) {
            uint32_t base = sb + nstg * GSTG;
            size_t go = (size_t)(c + 2) * 64;
            CP16(base + dA0, pAh + go); CP16(base + dA1, pAh + go + 16);
            CP16(base + GOFF_AL + dA0, pAl + go); CP16(base + GOFF_AL + dA1, pAl + go + 16);
            #pragma unroll
            for (int u = 0; u < 4; u++) {
                CP16(base + GOFF_BH + dB[u], pBh + go + u * 16);
                CP16(base + GOFF_BL + dB[u], pBl + go + u * 16);
            }
            CPCOMMIT();
        }
        nstg = nstg == 2 ? 0 : nstg + 1;

        const uint32_t sA = sb + stg * GSTG;
        #pragma unroll
        for (int kt = 0; kt < 2; kt++) {
            uint32_t ah[4][4], al[4][4];
            #pragma unroll
            for (int mi = 0; mi < 4; mi++) {
                uint32_t off = GSW((m0w + mi * 16 + (lane & 15)) * 64 + kt * 32 + (lane >> 4) * 16);
                ldsm4(ah[mi], sA + off);
                ldsm4(al[mi], sA + GOFF_AL + off);
            }
            #pragma unroll
            for (int nb = 0; nb < 4; nb++) {
                uint32_t bh[4], bl[4];
                uint32_t off = GSW((n0w + nb * 16 + brow) * 64 + kt * 32 + bcol);
                ldsm4(bh, sA + GOFF_BH + off);
                ldsm4(bl, sA + GOFF_BL + off);
                // term hi*hi (mi inner: acc reuse distance 8)
                #pragma unroll
                for (int mi = 0; mi < 4; mi++) {
                    mma16816(acc[mi][2 * nb],     ah[mi], bh);
                    mma16816(acc[mi][2 * nb + 1], ah[mi], bh + 2);
                }
                // term hi*lo
                #pragma unroll
                for (int mi = 0; mi < 4; mi++) {
                    mma16816(acc[mi][2 * nb],     ah[mi], bl);
                    mma16816(acc[mi][2 * nb + 1], ah[mi], bl + 2);
                }
                // term lo*hi
                #pragma unroll
                for (int mi = 0; mi < 4; mi++) {
                    mma16816(acc[mi][2 * nb],     al[mi], bh);
                    mma16816(acc[mi][2 * nb + 1], al[mi], bh + 2);
                }
            }
        }
        stg = stg == 2 ? 0 : stg + 1;
    }

    // ---- epilogue
    float* Cp = OUTBF ? nullptr : (Cmat + strideC * blockIdx.z);
    __nv_bfloat16* oh = OUTBF ? (obh + strideC * blockIdx.z) : nullptr;
    __nv_bfloat16* ol = OUTBF ? (obl + strideC * blockIdx.z) : nullptr;
    const float* Rp = RES ? (res + strideR * blockIdx.z) : nullptr;
    #pragma unroll
    for (int mi = 0; mi < 4; mi++) {
        int r0 = m0 + m0w + mi * 16 + (lane >> 2);
        float b0 = bias[r0], b1 = bias[r0 + 8];
        #pragma unroll
        for (int nb = 0; nb < 8; nb++) {
            int col = n0 + n0w + nb * 8 + (lane & 3) * 2;
            float2 v0 = { acc[mi][nb][0] + b0, acc[mi][nb][1] + b0 };
            float2 v1 = { acc[mi][nb][2] + b1, acc[mi][nb][3] + b1 };
            if (CLIP) {
                v0.x = fminf(10.f, fmaxf(-10.f, v0.x));
                v0.y = fminf(10.f, fmaxf(-10.f, v0.y));
                v1.x = fminf(10.f, fmaxf(-10.f, v1.x));
                v1.y = fminf(10.f, fmaxf(-10.f, v1.y));
            }
            if (RES) {
                float2 r0v = *(const float2*)(Rp + (size_t)r0 * N + col);
                float2 r1v = *(const float2*)(Rp + (size_t)(r0 + 8) * N + col);
                v0.x += r0v.x; v0.y += r0v.y;
                v1.x += r1v.x; v1.y += r1v.y;
            }
            if (OUTBF) {
                __nv_bfloat16 h0, l0, h1, l1;
                split_bf(v0.x, h0, l0); split_bf(v0.y, h1, l1);
                *(uint32_t*)(oh + (size_t)r0 * N + col) = packb(h0, h1);
                *(uint32_t*)(ol + (size_t)r0 * N + col) = packb(l0, l1);
                split_bf(v1.x, h0, l0); split_bf(v1.y, h1, l1);
                *(uint32_t*)(oh + (size_t)(r0 + 8) * N + col) = packb(h0, h1);
                *(uint32_t*)(ol + (size_t)(r0 + 8) * N + col) = packb(l0, l1);
            } else {
                *(float2*)(Cp + (size_t)r0 * N + col) = v0;
                *(float2*)(Cp + (size_t)(r0 + 8) * N + col) = v1;
            }
        }
    }
}

// ---------------------------------------------------------------------------
// Flash attention: 256 threads, 128 queries/CTA, trans-ldsm dataflow,
// 3-stage cp.async KV pipeline, term-major MMA order.
// Q staged through stage-0..1 buffers (4 x 8KB regions) then fragment-resident.
// ---------------------------------------------------------------------------
#define KVSTG 32768
#define OFF_KL 8192
#define OFF_VH 16384
#define OFF_VL 24576
#define ATTN_SMEM (3 * KVSTG)

__global__ __launch_bounds__(256) void attn_mma_kernel(
    const __nv_bfloat16* __restrict__ qkvh, const __nv_bfloat16* __restrict__ qkvl,
    __nv_bfloat16* __restrict__ aTh, __nv_bfloat16* __restrict__ aTl)
{
    extern __shared__ char sm[];
    const uint32_t sb = s2u(sm);
    const int tid = threadIdx.x;
    const int w = tid >> 5, lane = tid & 31;
    const int b = blockIdx.z, h = blockIdx.y;
    const int i0 = blockIdx.x * 128;

    const size_t bbase = (size_t)b * 3 * C_DIM;

    // ---- stage Q: 4 regions of 8KB: Qh(i<64), Qh(i>=64), Ql(i<64), Ql(i>=64)
    {
        const int qr = tid >> 2, qc = (tid & 3) * 16;   // d row, i elem (32B per thread)
        #pragma unroll
        for (int half = 0; half < 2; half++) {
            const char* sqh = (const char*)(qkvh + (bbase + h * 64 + qr) * L_DIM + i0 + half * 64 + qc);
            const char* sql = (const char*)(qkvl + (bbase + h * 64 + qr) * L_DIM + i0 + half * 64 + qc);
            uint32_t d0 = SW(qr * 128 + qc * 2), d1 = SW(qr * 128 + qc * 2 + 16);
            CP16(sb + half * 8192 + d0, sqh);
            CP16(sb + half * 8192 + d1, sqh + 16);
            CP16(sb + 16384 + half * 8192 + d0, sql);
            CP16(sb + 16384 + half * 8192 + d1, sql + 16);
        }
        CPCOMMIT();
    }
    CPWAIT0();
    __syncthreads();

    // ---- Q a-fragments via trans-ldsm (warp w -> i rows w*16..w*16+15)
    uint32_t qh[4][4], ql[4][4];
    {
        const uint32_t hofs = (w >> 2) * 8192;                    // i half
        const int rd = ((lane >> 4) << 3) + (lane & 7);
        const int ci = ((w & 3) << 4) + (((lane >> 3) & 1) << 3); // i col within half
        #pragma unroll
        for (int dt = 0; dt < 4; dt++) {
            uint32_t off = SW((dt * 16 + rd) * 128 + ci * 2);
            ldsm4t(qh[dt], sb + hofs + off);
            ldsm4t(ql[dt], sb + 16384 + hofs + off);
        }
    }
    __syncthreads();   // stage buffers free for KV pipeline

    // ---- KV loader mapping (rows = d 0..63, 128B rows of 64 j)
    const int kr = tid >> 2, kc = (tid & 3) * 16;
    const char* pKh = (const char*)(qkvh + (bbase + C_DIM + h * 64 + kr) * L_DIM + kc);
    const char* pKl = (const char*)(qkvl + (bbase + C_DIM + h * 64 + kr) * L_DIM + kc);
    const char* pVh = (const char*)(qkvh + (bbase + 2 * C_DIM + h * 64 + kr) * L_DIM + kc);
    const char* pVl = (const char*)(qkvl + (bbase + 2 * C_DIM + h * 64 + kr) * L_DIM + kc);
    const uint32_t dK0 = SW(kr * 128 + kc * 2), dK1 = SW(kr * 128 + kc * 2 + 16);

    #pragma unroll
    for (int tt = 0; tt < 2; tt++) {
        uint32_t base = sb + tt * KVSTG;
        size_t go = (size_t)tt * 128;
        CP16(base + dK0, pKh + go); CP16(base + dK1, pKh + go + 16);
        CP16(base + OFF_KL + dK0, pKl + go); CP16(base + OFF_KL + dK1, pKl + go + 16);
        CP16(base + OFF_VH + dK0, pVh + go); CP16(base + OFF_VH + dK1, pVh + go + 16);
        CP16(base + OFF_VL + dK0, pVl + go); CP16(base + OFF_VL + dK1, pVl + go + 16);
        CPCOMMIT();
    }

    const int krd = (((lane >> 3) & 1) << 3) + (lane & 7);
    const int kcj = (lane >> 4) << 3;
    const int brow = (lane & 7) + ((lane >> 4) << 3);
    const int bcol = ((lane >> 3) & 1) * 16;

    const float K1 = 0.125f * 1.44269504f;
    const float LIM = 10.0f * 1.44269504f;

    float oc[8][4] = {};
    float racc0 = 0.f, racc1 = 0.f;
    int stg = 0, nstg = 2;

    for (int t = 0; t < 32; t++) {
        CPWAIT1();
        __syncthreads();

        if (t + 2 < 32) {
            uint32_t base = sb + nstg * KVSTG;
            size_t go = (size_t)(t + 2) * 128;
            CP16(base + dK0, pKh + go); CP16(base + dK1, pKh + go + 16);
            CP16(base + OFF_KL + dK0, pKl + go); CP16(base + OFF_KL + dK1, pKl + go + 16);
            CP16(base + OFF_VH + dK0, pVh + go); CP16(base + OFF_VH + dK1, pVh + go + 16);
            CP16(base + OFF_VL + dK0, pVl + go); CP16(base + OFF_VL + dK1, pVl + go + 16);
            CPCOMMIT();
        }
        nstg = nstg == 2 ? 0 : nstg + 1;

        const uint32_t sKV = sb + stg * KVSTG;

        // ---- S = Q K^T, term-major (acc reuse distance 8)
        float sc[8][4] = {};
        #pragma unroll
        for (int dt = 0; dt < 4; dt++) {
            uint32_t kh[4][4], kl[4][4];
            #pragma unroll
            for (int jb = 0; jb < 4; jb++) {
                uint32_t off = SW((dt * 16 + krd) * 128 + (jb * 16 + kcj) * 2);
                ldsm4t(kh[jb], sKV + off);
                ldsm4t(kl[jb], sKV + OFF_KL + off);
            }
            #pragma unroll
            for (int jb = 0; jb < 4; jb++) {
                mma16816(sc[2 * jb],     qh[dt], kh[jb]);
                mma16816(sc[2 * jb + 1], qh[dt], kh[jb] + 2);
            }
            #pragma unroll
            for (int jb = 0; jb < 4; jb++) {
                mma16816(sc[2 * jb],     qh[dt], kl[jb]);
                mma16816(sc[2 * jb + 1], qh[dt], kl[jb] + 2);
            }
            #pragma unroll
            for (int jb = 0; jb < 4; jb++) {
                mma16816(sc[2 * jb],     ql[dt], kh[jb]);
                mma16816(sc[2 * jb + 1], ql[dt], kh[jb] + 2);
            }
        }

        // ---- softmax numerator
        #pragma unroll
        for (int nt = 0; nt < 8; nt++) {
            #pragma unroll
            for (int k = 0; k < 4; k++) {
                float y = sc[nt][k] * K1;
                y = fminf(LIM, fmaxf(-LIM, y));
                float p = exp2_poly(y);
                sc[nt][k] = p;
                if (k < 2) racc0 += p; else racc1 += p;
            }
        }

        // ---- pack P fragments from registers
        uint32_t ph[4][4], pl[4][4];
        #pragma unroll
        for (int q = 0; q < 4; q++) {
            __nv_bfloat16 h0, l0, h1, l1;
            split_bf(sc[2 * q][0], h0, l0); split_bf(sc[2 * q][1], h1, l1);
            ph[q][0] = packb(h0, h1); pl[q][0] = packb(l0, l1);
            split_bf(sc[2 * q][2], h0, l0); split_bf(sc[2 * q][3], h1, l1);
            ph[q][1] = packb(h0, h1); pl[q][1] = packb(l0, l1);
            split_bf(sc[2 * q + 1][0], h0, l0); split_bf(sc[2 * q + 1][1], h1, l1);
            ph[q][2] = packb(h0, h1); pl[q][2] = packb(l0, l1);
            split_bf(sc[2 * q + 1][2], h0, l0); split_bf(sc[2 * q + 1][3], h1, l1);
            ph[q][3] = packb(h0, h1); pl[q][3] = packb(l0, l1);
        }

        // ---- O += P V^T, term-major (acc reuse distance 8)
        #pragma unroll
        for (int kt = 0; kt < 4; kt++) {
            uint32_t vvh[4][4], vvl[4][4];
            #pragma unroll
            for (int db = 0; db < 4; db++) {
                uint32_t off = SW((db * 16 + brow) * 128 + kt * 32 + bcol);
                ldsm4(vvh[db], sKV + OFF_VH + off);
                ldsm4(vvl[db], sKV + OFF_VL + off);
            }
            #pragma unroll
            for (int db = 0; db < 4; db++) {
                mma16816(oc[2 * db],     ph[kt], vvh[db]);
                mma16816(oc[2 * db + 1], ph[kt], vvh[db] + 2);
            }
            #pragma unroll
            for (int db = 0; db < 4; db++) {
                mma16816(oc[2 * db],     ph[kt], vvl[db]);
                mma16816(oc[2 * db + 1], ph[kt], vvl[db] + 2);
            }
            #pragma unroll
            for (int db = 0; db < 4; db++) {
                mma16816(oc[2 * db],     pl[kt], vvh[db]);
                mma16816(oc[2 * db + 1], pl[kt], vvh[db] + 2);
            }
        }
        stg = stg == 2 ? 0 : stg + 1;
    }

    // ---- row denominators (quad reduce)
    racc0 += __shfl_xor_sync(0xffffffffu, racc0, 1);
    racc0 += __shfl_xor_sync(0xffffffffu, racc0, 2);
    racc1 += __shfl_xor_sync(0xffffffffu, racc1, 1);
    racc1 += __shfl_xor_sync(0xffffffffu, racc1, 2);
    const float inv0 = 1.0f / racc0;
    const float inv1 = 1.0f / racc1;

    // ---- write att^T hi/lo bf16: [b][l][c], c = h*64 + d
    const int ibase = i0 + w * 16 + (lane >> 2);
    const size_t rowbase = ((size_t)b * L_DIM + ibase) * C_DIM + h * 64;
    #pragma unroll
    for (int nt = 0; nt < 8; nt++) {
        int d = nt * 8 + 2 * (lane & 3);
        float a0 = oc[nt][0] * inv0, a1 = oc[nt][1] * inv0;
        float a2 = oc[nt][2] * inv1, a3 = oc[nt][3] * inv1;
        __nv_bfloat16 h0, l0, h1, l1;
        split_bf(a0, h0, l0); split_bf(a1, h1, l1);
        *(uint32_t*)(aTh + rowbase + d) = packb(h0, h1);
        *(uint32_t*)(aTl + rowbase + d) = packb(l0, l1);
        split_bf(a2, h0, l0); split_bf(a3, h1, l1);
        *(uint32_t*)(aTh + rowbase + (size_t)8 * C_DIM + d) = packb(h0, h1);
        *(uint32_t*)(aTl + rowbase + (size_t)8 * C_DIM + d) = packb(l0, l1);
    }
}

// ---------------------------------------------------------------------------
// GroupNorm (proven)
// ---------------------------------------------------------------------------
__global__ __launch_bounds__(256) void gn_kernel(
    const float* __restrict__ z, const float* __restrict__ gamma,
    const float* __restrict__ beta, float* __restrict__ outp)
{
    const int bg = blockIdx.x;
    const int b = bg >> 5, g = bg & 31;
    const float* zp = z + ((size_t)b * C_DIM + g * 16) * L_DIM;
    float* op = outp + ((size_t)b * C_DIM + g * 16) * L_DIM;
    const int t = threadIdx.x;

    float s = 0.f, ss = 0.f;
    const float4* z4 = (const float4*)zp;
    for (int i = t; i < 8192; i += 256) {
        float4 v = z4[i];
        s  += v.x + v.y + v.z + v.w;
        ss += v.x * v.x + v.y * v.y + v.z * v.z + v.w * v.w;
    }
    __shared__ float rs[8], rss[8];
    __shared__ float smu, srstd;
    #pragma unroll
    for (int o = 16; o; o >>= 1) {
        s  += __shfl_xor_sync(0xffffffffu, s, o);
        ss += __shfl_xor_sync(0xffffffffu, ss, o);
    }
    if ((t & 31) == 0) { rs[t >> 5] = s; rss[t >> 5] = ss; }
    __syncthreads();
    if (t == 0) {
        float ts = 0.f, tss = 0.f;
        #pragma unroll
        for (int wv = 0; wv < 8; wv++) { ts += rs[wv]; tss += rss[wv]; }
        float mu = ts * (1.f / 32768.f);
        float var = tss * (1.f / 32768.f) - mu * mu;
        smu = mu;
        srstd = rsqrtf(var + 1e-5f);
    }
    __syncthreads();
    const float mu = smu, rstd = srstd;
    float4* o4 = (float4*)op;
    for (int i = t; i < 8192; i += 256) {
        int ch = g * 16 + (i >> 9);
        float ga = gamma[ch] * rstd;
        float be = beta[ch];
        float4 v = z4[i];
        v.x = (v.x - mu) * ga + be;
        v.y = (v.y - mu) * ga + be;
        v.z = (v.z - mu) * ga + be;
        v.w = (v.w - mu) * ga + be;
        o4[i] = v;
    }
}

// ---------------------------------------------------------------------------
extern "C" void kernel_launch(void* const* d_in, const int* in_sizes, int n_in,
                              void* d_out, int out_size)
{
    const float* x     = (const float*)d_in[0];
    const float* Wqkv  = (const float*)d_in[1];
    const float* bqkv  = (const float*)d_in[2];
    const float* Wproj = (const float*)d_in[3];
    const float* bproj = (const float*)d_in[4];
    const float* gamma = (const float*)d_in[5];
    const float* beta  = (const float*)d_in[6];
    float* out = (float*)d_out;

    float* zbuf;
    __nv_bfloat16 *qkvh, *qkvl, *xTh, *xTl, *aTh, *aTl, *wqh, *wql, *wph, *wpl;
    cudaGetSymbolAddress((void**)&zbuf, g_z);
    cudaGetSymbolAddress((void**)&qkvh, g_qkvh);
    cudaGetSymbolAddress((void**)&qkvl, g_qkvl);
    cudaGetSymbolAddress((void**)&xTh,  g_xTh);
    cudaGetSymbolAddress((void**)&xTl,  g_xTl);
    cudaGetSymbolAddress((void**)&aTh,  g_aTh);
    cudaGetSymbolAddress((void**)&aTl,  g_aTl);
    cudaGetSymbolAddress((void**)&wqh,  g_wqh);
    cudaGetSymbolAddress((void**)&wql,  g_wql);
    cudaGetSymbolAddress((void**)&wph,  g_wph);
    cudaGetSymbolAddress((void**)&wpl,  g_wpl);

    cudaFuncSetAttribute(attn_mma_kernel, cudaFuncAttributeMaxDynamicSharedMemorySize, ATTN_SMEM);
    cudaFuncSetAttribute(mma_gemm_kernel<true, false, true>,  cudaFuncAttributeMaxDynamicSharedMemorySize, GEMM_SMEM);
    cudaFuncSetAttribute(mma_gemm_kernel<false, true, false>, cudaFuncAttributeMaxDynamicSharedMemorySize, GEMM_SMEM);

    // pre-split inputs
    tsplit_x_kernel<<<dim3(16, 8, BATCH), 256>>>(x, xTh, xTl);
    esplit_kernel<<<(3 * C_DIM * C_DIM / 4 + 255) / 256, 256>>>(Wqkv, wqh, wql, 3 * C_DIM * C_DIM / 4);
    esplit_kernel<<<(C_DIM * C_DIM / 4 + 255) / 256, 256>>>(Wproj, wph, wpl, C_DIM * C_DIM / 4);

    // qkv = clip(Wqkv @ x + bqkv) -> bf16 hi/lo [b][3C][L]
    mma_gemm_kernel<true, false, true><<<dim3(8, 12, BATCH), 256, GEMM_SMEM>>>(
        wqh, wql, xTh, xTl, nullptr, qkvh, qkvl, bqkv, nullptr,
        L_DIM, C_DIM, (size_t)CL, (size_t)3 * CL, 0);

    // attention -> att^T hi/lo bf16
    attn_mma_kernel<<<dim3(16, HEADS, BATCH), 256, ATTN_SMEM>>>(qkvh, qkvl, aTh, aTl);

    // z = Wproj @ att + bproj + x
    mma_gemm_kernel<false, true, false><<<dim3(8, 4, BATCH), 256, GEMM_SMEM>>>(
        wph, wpl, aTh, aTl, zbuf, nullptr, nullptr, bproj, x,
        L_DIM, C_DIM, (size_t)CL, (size_t)CL, (size_t)CL);

    // out = groupnorm(z)
    gn_kernel<<<dim3(BATCH * 32), 256>>>(zbuf, gamma, beta, out);
}

// round 16
// speedup vs baseline: 1.1380x; 1.0779x over previous
#include <cuda_runtime.h>
#include <cuda_bf16.h>
#include <cstdint>

#define C_DIM 512
#define L_DIM 2048
#define BATCH 4
#define HEADS 8
#define HDIM 64
#define CL (C_DIM * L_DIM)

// ---------------------------------------------------------------------------
// Helpers
// ---------------------------------------------------------------------------
__device__ __forceinline__ uint32_t s2u(const void* p) {
    uint32_t a;
    asm("{ .reg .u64 t; cvta.to.shared.u64 t, %1; cvt.u32.u64 %0, t; }" : "=r"(a) : "l"(p));
    return a;
}
__device__ __forceinline__ void ldsm4(uint32_t* r, uint32_t a) {
    asm volatile("ldmatrix.sync.aligned.m8n8.x4.shared.b16 {%0,%1,%2,%3}, [%4];"
                 : "=r"(r[0]), "=r"(r[1]), "=r"(r[2]), "=r"(r[3]) : "r"(a));
}
__device__ __forceinline__ void ldsm4t(uint32_t* r, uint32_t a) {
    asm volatile("ldmatrix.sync.aligned.m8n8.x4.trans.shared.b16 {%0,%1,%2,%3}, [%4];"
                 : "=r"(r[0]), "=r"(r[1]), "=r"(r[2]), "=r"(r[3]) : "r"(a));
}
__device__ __forceinline__ void mma16816(float* c, const uint32_t* a, const uint32_t* b) {
    asm volatile("mma.sync.aligned.m16n8k16.row.col.f32.bf16.bf16.f32 "
                 "{%0,%1,%2,%3}, {%4,%5,%6,%7}, {%8,%9}, {%0,%1,%2,%3};"
                 : "+f"(c[0]), "+f"(c[1]), "+f"(c[2]), "+f"(c[3])
                 : "r"(a[0]), "r"(a[1]), "r"(a[2]), "r"(a[3]), "r"(b[0]), "r"(b[1]));
}
#define CP16(dst, src)  asm volatile("cp.async.cg.shared.global [%0], [%1], 16;" :: "r"(dst), "l"(src))
#define CPCOMMIT()      asm volatile("cp.async.commit_group;")
#define CPWAIT1()       asm volatile("cp.async.wait_group 1;" ::: "memory")
#define CPWAIT0()       asm volatile("cp.async.wait_group 0;" ::: "memory")
#define SW(x)  ((x) ^ (((x) >> 3) & 0x70))
#define GSW(x) ((x) ^ (((x) >> 3) & 0x30))
__device__ __forceinline__ void split_bf(float x, __nv_bfloat16& h, __nv_bfloat16& l) {
    h = __float2bfloat16(x);
    l = __float2bfloat16(x - __bfloat162float(h));
}
__device__ __forceinline__ uint32_t packb(__nv_bfloat16 a, __nv_bfloat16 b) {
    __nv_bfloat162 t(a, b);
    return *(uint32_t*)&t;
}
// exp2 via FFMA/ALU only (no MUFU). |y| <= 14.5 guaranteed by clip.
__device__ __forceinline__ float exp2_poly(float y) {
    float r = y + 12582912.f;
    int n = __float_as_int(r) - 0x4B400000;
    float f = y - (r - 12582912.f);
    float p = 0.0013333558f;
    p = p * f + 0.0096181291f;
    p = p * f + 0.0555041087f;
    p = p * f + 0.2402265069f;
    p = p * f + 0.6931471825f;
    p = p * f + 1.0f;
    return __int_as_float(__float_as_int(p) + (n << 23));
}

// ---------------------------------------------------------------------------
// Scratch
// ---------------------------------------------------------------------------
__device__ float g_z[BATCH * CL];
__device__ __nv_bfloat16 g_qkvh[BATCH * 3 * CL], g_qkvl[BATCH * 3 * CL];  // [b][3C][L]
__device__ __nv_bfloat16 g_xTh[BATCH * CL], g_xTl[BATCH * CL];            // x^T [b][l][c]
__device__ __nv_bfloat16 g_aTh[BATCH * CL], g_aTl[BATCH * CL];            // att^T [b][l][c]
__device__ __nv_bfloat16 g_wqh[3 * C_DIM * C_DIM], g_wql[3 * C_DIM * C_DIM];
__device__ __nv_bfloat16 g_wph[C_DIM * C_DIM], g_wpl[C_DIM * C_DIM];

// ---------------------------------------------------------------------------
// Elementwise fp32 -> bf16 hi/lo split
// ---------------------------------------------------------------------------
__global__ __launch_bounds__(256) void esplit_kernel(
    const float* __restrict__ s, __nv_bfloat16* __restrict__ dh,
    __nv_bfloat16* __restrict__ dl, int n4)
{
    int i = blockIdx.x * 256 + threadIdx.x;
    if (i >= n4) return;
    float4 v = ((const float4*)s)[i];
    __nv_bfloat16 h0, l0, h1, l1, h2, l2, h3, l3;
    split_bf(v.x, h0, l0); split_bf(v.y, h1, l1);
    split_bf(v.z, h2, l2); split_bf(v.w, h3, l3);
    uint2 wh = { packb(h0, h1), packb(h2, h3) };
    uint2 wl = { packb(l0, l1), packb(l2, l3) };
    ((uint2*)dh)[i] = wh;
    ((uint2*)dl)[i] = wl;
}

// ---------------------------------------------------------------------------
// Transpose + split x: fp32 [64r][128c of L] -> bf16 hi/lo [128 l][64 c]
// ---------------------------------------------------------------------------
__global__ __launch_bounds__(256) void tsplit_x_kernel(
    const float* __restrict__ x, __nv_bfloat16* __restrict__ dh, __nv_bfloat16* __restrict__ dl)
{
    __shared__ __nv_bfloat16 th[128 * 64], tl[128 * 64];
    const int lc = blockIdx.x, cc = blockIdx.y, b = blockIdx.z;
    const float* src = x + ((size_t)b * C_DIM + cc * 64) * L_DIM + lc * 128;
    size_t doff = ((size_t)b * L_DIM + lc * 128) * C_DIM + cc * 64;
    __nv_bfloat16* dhp = dh + doff;
    __nv_bfloat16* dlp = dl + doff;
    const int t = threadIdx.x;
    {
        int r = t >> 2, cb = (t & 3) * 32;
        const float4* s4 = (const float4*)(src + (size_t)r * L_DIM + cb);
        #pragma unroll
        for (int u = 0; u < 8; u++) {
            float4 v = s4[u];
            float vv[4] = {v.x, v.y, v.z, v.w};
            #pragma unroll
            for (int e = 0; e < 4; e++) {
                int c = cb + 4 * u + e;
                __nv_bfloat16 hb, lb; split_bf(vv[e], hb, lb);
                th[c * 64 + r] = hb;
                tl[c * 64 + r] = lb;
            }
        }
    }
    __syncthreads();
    {
        int l = t >> 1, eo = (t & 1) * 32;
        #pragma unroll
        for (int u = 0; u < 4; u++) {
            *(uint4*)(dhp + (size_t)l * C_DIM + eo + 8 * u) = *(uint4*)&th[l * 64 + eo + 8 * u];
            *(uint4*)(dlp + (size_t)l * C_DIM + eo + 8 * u) = *(uint4*)&tl[l * 64 + eo + 8 * u];
        }
    }
}

// ---------------------------------------------------------------------------
// Tensor-core GEMM: 512 threads (16 warps -> 4/SMSP), warp tile 32x64,
// CTA tile 128x256, BK=32, cp.async 3-stage.
// ---------------------------------------------------------------------------
#define GSTG 49152
#define GOFF_AL 8192
#define GOFF_BH 16384
#define GOFF_BL 32768
#define GEMM_SMEM (3 * GSTG)

template<bool CLIP, bool RES, bool OUTBF>
__global__ __launch_bounds__(512) void mma_gemm_kernel(
    const __nv_bfloat16* __restrict__ Ah, const __nv_bfloat16* __restrict__ Al,
    const __nv_bfloat16* __restrict__ Bh, const __nv_bfloat16* __restrict__ Bl,
    float* __restrict__ Cmat, __nv_bfloat16* __restrict__ obh, __nv_bfloat16* __restrict__ obl,
    const float* __restrict__ bias, const float* __restrict__ res,
    int N, int K, size_t strideB, size_t strideC, size_t strideR)
{
    extern __shared__ char gsm[];
    const uint32_t sb = s2u(gsm);

    const int t = threadIdx.x;
    const int warp = t >> 5, lane = t & 31;
    const int wm = warp & 3, wn = warp >> 2;
    const int m0w = wm * 32, n0w = wn * 64;
    const int n0 = blockIdx.x * 256, m0 = blockIdx.y * 128;

    // loader mapping (512 threads): A 128 rows x 64B (1 CP16/thr/buf), B 256 rows x 64B (2/thr/buf)
    const int ar = t >> 2, aco = (t & 3) * 16;
    const int br = t >> 1, bco = (t & 1) * 32;
    const char* pAh = (const char*)(Ah + (size_t)(m0 + ar) * K) + aco;
    const char* pAl = (const char*)(Al + (size_t)(m0 + ar) * K) + aco;
    const char* pBh = (const char*)(Bh + strideB * blockIdx.z + (size_t)(n0 + br) * K) + bco;
    const char* pBl = (const char*)(Bl + strideB * blockIdx.z + (size_t)(n0 + br) * K) + bco;
    const uint32_t dA0 = GSW(ar * 64 + aco);
    const uint32_t dB0 = GSW(br * 64 + bco), dB1 = GSW(br * 64 + bco + 16);

    const int brow = (lane & 7) + ((lane >> 4) << 3);
    const int bcol = ((lane >> 3) & 1) * 16;

    const int NCH = K >> 5;

    #pragma unroll
    for (int c = 0; c < 2; c++) {
        uint32_t base = sb + c * GSTG;
        size_t go = (size_t)c * 64;
        CP16(base + dA0, pAh + go);
        CP16(base + GOFF_AL + dA0, pAl + go);
        CP16(base + GOFF_BH + dB0, pBh + go);
        CP16(base + GOFF_BH + dB1, pBh + go + 16);
        CP16(base + GOFF_BL + dB0, pBl + go);
        CP16(base + GOFF_BL + dB1, pBl + go + 16);
        CPCOMMIT();
    }

    float acc[2][8][4] = {};
    int stg = 0, nstg = 2;

    for (int c = 0; c < NCH; c++) {
        CPWAIT1();
        __syncthreads();

        if (c + 2 < NCH) {
            uint32_t base = sb + nstg * GSTG;
            size_t go = (size_t)(c + 2) * 64;
            CP16(base + dA0, pAh + go);
            CP16(base + GOFF_AL + dA0, pAl + go);
            CP16(base + GOFF_BH + dB0, pBh + go);
            CP16(base + GOFF_BH + dB1, pBh + go + 16);
            CP16(base + GOFF_BL + dB0, pBl + go);
            CP16(base + GOFF_BL + dB1, pBl + go + 16);
            CPCOMMIT();
        }
        nstg = nstg == 2 ? 0 : nstg + 1;

        const uint32_t sA = sb + stg * GSTG;
        #pragma unroll
        for (int kt = 0; kt < 2; kt++) {
            uint32_t ah[2][4], al[2][4];
            #pragma unroll
            for (int mi = 0; mi < 2; mi++) {
                uint32_t off = GSW((m0w + mi * 16 + (lane & 15)) * 64 + kt * 32 + (lane >> 4) * 16);
                ldsm4(ah[mi], sA + off);
                ldsm4(al[mi], sA + GOFF_AL + off);
            }
            #pragma unroll
            for (int nb = 0; nb < 4; nb++) {
                uint32_t bh[4], bl[4];
                uint32_t off = GSW((n0w + nb * 16 + brow) * 64 + kt * 32 + bcol);
                ldsm4(bh, sA + GOFF_BH + off);
                ldsm4(bl, sA + GOFF_BL + off);
                #pragma unroll
                for (int mi = 0; mi < 2; mi++) {
                    mma16816(acc[mi][2 * nb],     ah[mi], bh);
                    mma16816(acc[mi][2 * nb + 1], ah[mi], bh + 2);
                }
                #pragma unroll
                for (int mi = 0; mi < 2; mi++) {
                    mma16816(acc[mi][2 * nb],     ah[mi], bl);
                    mma16816(acc[mi][2 * nb + 1], ah[mi], bl + 2);
                }
                #pragma unroll
                for (int mi = 0; mi < 2; mi++) {
                    mma16816(acc[mi][2 * nb],     al[mi], bh);
                    mma16816(acc[mi][2 * nb + 1], al[mi], bh + 2);
                }
            }
        }
        stg = stg == 2 ? 0 : stg + 1;
    }

    // ---- epilogue
    float* Cp = OUTBF ? nullptr : (Cmat + strideC * blockIdx.z);
    __nv_bfloat16* oh = OUTBF ? (obh + strideC * blockIdx.z) : nullptr;
    __nv_bfloat16* ol = OUTBF ? (obl + strideC * blockIdx.z) : nullptr;
    const float* Rp = RES ? (res + strideR * blockIdx.z) : nullptr;
    #pragma unroll
    for (int mi = 0; mi < 2; mi++) {
        int r0 = m0 + m0w + mi * 16 + (lane >> 2);
        float b0 = bias[r0], b1 = bias[r0 + 8];
        #pragma unroll
        for (int nb = 0; nb < 8; nb++) {
            int col = n0 + n0w + nb * 8 + (lane & 3) * 2;
            float2 v0 = { acc[mi][nb][0] + b0, acc[mi][nb][1] + b0 };
            float2 v1 = { acc[mi][nb][2] + b1, acc[mi][nb][3] + b1 };
            if (CLIP) {
                v0.x = fminf(10.f, fmaxf(-10.f, v0.x));
                v0.y = fminf(10.f, fmaxf(-10.f, v0.y));
                v1.x = fminf(10.f, fmaxf(-10.f, v1.x));
                v1.y = fminf(10.f, fmaxf(-10.f, v1.y));
            }
            if (RES) {
                float2 r0v = *(const float2*)(Rp + (size_t)r0 * N + col);
                float2 r1v = *(const float2*)(Rp + (size_t)(r0 + 8) * N + col);
                v0.x += r0v.x; v0.y += r0v.y;
                v1.x += r1v.x; v1.y += r1v.y;
            }
            if (OUTBF) {
                __nv_bfloat16 h0, l0, h1, l1;
                split_bf(v0.x, h0, l0); split_bf(v0.y, h1, l1);
                *(uint32_t*)(oh + (size_t)r0 * N + col) = packb(h0, h1);
                *(uint32_t*)(ol + (size_t)r0 * N + col) = packb(l0, l1);
                split_bf(v1.x, h0, l0); split_bf(v1.y, h1, l1);
                *(uint32_t*)(oh + (size_t)(r0 + 8) * N + col) = packb(h0, h1);
                *(uint32_t*)(ol + (size_t)(r0 + 8) * N + col) = packb(l0, l1);
            } else {
                *(float2*)(Cp + (size_t)r0 * N + col) = v0;
                *(float2*)(Cp + (size_t)(r0 + 8) * N + col) = v1;
            }
        }
    }
}

// ---------------------------------------------------------------------------
// Flash attention (R15 version, proven): 256 threads, 128 queries/CTA,
// trans-ldsm dataflow, 3-stage cp.async KV pipeline, term-major MMA order.
// ---------------------------------------------------------------------------
#define KVSTG 32768
#define OFF_KL 8192
#define OFF_VH 16384
#define OFF_VL 24576
#define ATTN_SMEM (3 * KVSTG)

__global__ __launch_bounds__(256) void attn_mma_kernel(
    const __nv_bfloat16* __restrict__ qkvh, const __nv_bfloat16* __restrict__ qkvl,
    __nv_bfloat16* __restrict__ aTh, __nv_bfloat16* __restrict__ aTl)
{
    extern __shared__ char sm[];
    const uint32_t sb = s2u(sm);
    const int tid = threadIdx.x;
    const int w = tid >> 5, lane = tid & 31;
    const int b = blockIdx.z, h = blockIdx.y;
    const int i0 = blockIdx.x * 128;

    const size_t bbase = (size_t)b * 3 * C_DIM;

    // ---- stage Q: 4 regions of 8KB: Qh(i<64), Qh(i>=64), Ql(i<64), Ql(i>=64)
    {
        const int qr = tid >> 2, qc = (tid & 3) * 16;
        #pragma unroll
        for (int half = 0; half < 2; half++) {
            const char* sqh = (const char*)(qkvh + (bbase + h * 64 + qr) * L_DIM + i0 + half * 64 + qc);
            const char* sql = (const char*)(qkvl + (bbase + h * 64 + qr) * L_DIM + i0 + half * 64 + qc);
            uint32_t d0 = SW(qr * 128 + qc * 2), d1 = SW(qr * 128 + qc * 2 + 16);
            CP16(sb + half * 8192 + d0, sqh);
            CP16(sb + half * 8192 + d1, sqh + 16);
            CP16(sb + 16384 + half * 8192 + d0, sql);
            CP16(sb + 16384 + half * 8192 + d1, sql + 16);
        }
        CPCOMMIT();
    }
    CPWAIT0();
    __syncthreads();

    // ---- Q a-fragments via trans-ldsm
    uint32_t qh[4][4], ql[4][4];
    {
        const uint32_t hofs = (w >> 2) * 8192;
        const int rd = ((lane >> 4) << 3) + (lane & 7);
        const int ci = ((w & 3) << 4) + (((lane >> 3) & 1) << 3);
        #pragma unroll
        for (int dt = 0; dt < 4; dt++) {
            uint32_t off = SW((dt * 16 + rd) * 128 + ci * 2);
            ldsm4t(qh[dt], sb + hofs + off);
            ldsm4t(ql[dt], sb + 16384 + hofs + off);
        }
    }
    __syncthreads();

    // ---- KV loader mapping
    const int kr = tid >> 2, kc = (tid & 3) * 16;
    const char* pKh = (const char*)(qkvh + (bbase + C_DIM + h * 64 + kr) * L_DIM + kc);
    const char* pKl = (const char*)(qkvl + (bbase + C_DIM + h * 64 + kr) * L_DIM + kc);
    const char* pVh = (const char*)(qkvh + (bbase + 2 * C_DIM + h * 64 + kr) * L_DIM + kc);
    const char* pVl = (const char*)(qkvl + (bbase + 2 * C_DIM + h * 64 + kr) * L_DIM + kc);
    const uint32_t dK0 = SW(kr * 128 + kc * 2), dK1 = SW(kr * 128 + kc * 2 + 16);

    #pragma unroll
    for (int tt = 0; tt < 2; tt++) {
        uint32_t base = sb + tt * KVSTG;
        size_t go = (size_t)tt * 128;
        CP16(base + dK0, pKh + go); CP16(base + dK1, pKh + go + 16);
        CP16(base + OFF_KL + dK0, pKl + go); CP16(base + OFF_KL + dK1, pKl + go + 16);
        CP16(base + OFF_VH + dK0, pVh + go); CP16(base + OFF_VH + dK1, pVh + go + 16);
        CP16(base + OFF_VL + dK0, pVl + go); CP16(base + OFF_VL + dK1, pVl + go + 16);
        CPCOMMIT();
    }

    const int krd = (((lane >> 3) & 1) << 3) + (lane & 7);
    const int kcj = (lane >> 4) << 3;
    const int brow = (lane & 7) + ((lane >> 4) << 3);
    const int bcol = ((lane >> 3) & 1) * 16;

    const float K1 = 0.125f * 1.44269504f;
    const float LIM = 10.0f * 1.44269504f;

    float oc[8][4] = {};
    float racc0 = 0.f, racc1 = 0.f;
    int stg = 0, nstg = 2;

    for (int t = 0; t < 32; t++) {
        CPWAIT1();
        __syncthreads();

        if (t + 2 < 32) {
            uint32_t base = sb + nstg * KVSTG;
            size_t go = (size_t)(t + 2) * 128;
            CP16(base + dK0, pKh + go); CP16(base + dK1, pKh + go + 16);
            CP16(base + OFF_KL + dK0, pKl + go); CP16(base + OFF_KL + dK1, pKl + go + 16);
            CP16(base + OFF_VH + dK0, pVh + go); CP16(base + OFF_VH + dK1, pVh + go + 16);
            CP16(base + OFF_VL + dK0, pVl + go); CP16(base + OFF_VL + dK1, pVl + go + 16);
            CPCOMMIT();
        }
        nstg = nstg == 2 ? 0 : nstg + 1;

        const uint32_t sKV = sb + stg * KVSTG;

        // ---- S = Q K^T, term-major
        float sc[8][4] = {};
        #pragma unroll
        for (int dt = 0; dt < 4; dt++) {
            uint32_t kh[4][4], kl[4][4];
            #pragma unroll
            for (int jb = 0; jb < 4; jb++) {
                uint32_t off = SW((dt * 16 + krd) * 128 + (jb * 16 + kcj) * 2);
                ldsm4t(kh[jb], sKV + off);
                ldsm4t(kl[jb], sKV + OFF_KL + off);
            }
            #pragma unroll
            for (int jb = 0; jb < 4; jb++) {
                mma16816(sc[2 * jb],     qh[dt], kh[jb]);
                mma16816(sc[2 * jb + 1], qh[dt], kh[jb] + 2);
            }
            #pragma unroll
            for (int jb = 0; jb < 4; jb++) {
                mma16816(sc[2 * jb],     qh[dt], kl[jb]);
                mma16816(sc[2 * jb + 1], qh[dt], kl[jb] + 2);
            }
            #pragma unroll
            for (int jb = 0; jb < 4; jb++) {
                mma16816(sc[2 * jb],     ql[dt], kh[jb]);
                mma16816(sc[2 * jb + 1], ql[dt], kh[jb] + 2);
            }
        }

        // ---- softmax numerator
        #pragma unroll
        for (int nt = 0; nt < 8; nt++) {
            #pragma unroll
            for (int k = 0; k < 4; k++) {
                float y = sc[nt][k] * K1;
                y = fminf(LIM, fmaxf(-LIM, y));
                float p = exp2_poly(y);
                sc[nt][k] = p;
                if (k < 2) racc0 += p; else racc1 += p;
            }
        }

        // ---- pack P fragments
        uint32_t ph[4][4], pl[4][4];
        #pragma unroll
        for (int q = 0; q < 4; q++) {
            __nv_bfloat16 h0, l0, h1, l1;
            split_bf(sc[2 * q][0], h0, l0); split_bf(sc[2 * q][1], h1, l1);
            ph[q][0] = packb(h0, h1); pl[q][0] = packb(l0, l1);
            split_bf(sc[2 * q][2], h0, l0); split_bf(sc[2 * q][3], h1, l1);
            ph[q][1] = packb(h0, h1); pl[q][1] = packb(l0, l1);
            split_bf(sc[2 * q + 1][0], h0, l0); split_bf(sc[2 * q + 1][1], h1, l1);
            ph[q][2] = packb(h0, h1); pl[q][2] = packb(l0, l1);
            split_bf(sc[2 * q + 1][2], h0, l0); split_bf(sc[2 * q + 1][3], h1, l1);
            ph[q][3] = packb(h0, h1); pl[q][3] = packb(l0, l1);
        }

        // ---- O += P V^T, term-major
        #pragma unroll
        for (int kt = 0; kt < 4; kt++) {
            uint32_t vvh[4][4], vvl[4][4];
            #pragma unroll
            for (int db = 0; db < 4; db++) {
                uint32_t off = SW((db * 16 + brow) * 128 + kt * 32 + bcol);
                ldsm4(vvh[db], sKV + OFF_VH + off);
                ldsm4(vvl[db], sKV + OFF_VL + off);
            }
            #pragma unroll
            for (int db = 0; db < 4; db++) {
                mma16816(oc[2 * db],     ph[kt], vvh[db]);
                mma16816(oc[2 * db + 1], ph[kt], vvh[db] + 2);
            }
            #pragma unroll
            for (int db = 0; db < 4; db++) {
                mma16816(oc[2 * db],     ph[kt], vvl[db]);
                mma16816(oc[2 * db + 1], ph[kt], vvl[db] + 2);
            }
            #pragma unroll
            for (int db = 0; db < 4; db++) {
                mma16816(oc[2 * db],     pl[kt], vvh[db]);
                mma16816(oc[2 * db + 1], pl[kt], vvh[db] + 2);
            }
        }
        stg = stg == 2 ? 0 : stg + 1;
    }

    // ---- row denominators (quad reduce)
    racc0 += __shfl_xor_sync(0xffffffffu, racc0, 1);
    racc0 += __shfl_xor_sync(0xffffffffu, racc0, 2);
    racc1 += __shfl_xor_sync(0xffffffffu, racc1, 1);
    racc1 += __shfl_xor_sync(0xffffffffu, racc1, 2);
    const float inv0 = 1.0f / racc0;
    const float inv1 = 1.0f / racc1;

    // ---- write att^T hi/lo bf16: [b][l][c], c = h*64 + d
    const int ibase = i0 + w * 16 + (lane >> 2);
    const size_t rowbase = ((size_t)b * L_DIM + ibase) * C_DIM + h * 64;
    #pragma unroll
    for (int nt = 0; nt < 8; nt++) {
        int d = nt * 8 + 2 * (lane & 3);
        float a0 = oc[nt][0] * inv0, a1 = oc[nt][1] * inv0;
        float a2 = oc[nt][2] * inv1, a3 = oc[nt][3] * inv1;
        __nv_bfloat16 h0, l0, h1, l1;
        split_bf(a0, h0, l0); split_bf(a1, h1, l1);
        *(uint32_t*)(aTh + rowbase + d) = packb(h0, h1);
        *(uint32_t*)(aTl + rowbase + d) = packb(l0, l1);
        split_bf(a2, h0, l0); split_bf(a3, h1, l1);
        *(uint32_t*)(aTh + rowbase + (size_t)8 * C_DIM + d) = packb(h0, h1);
        *(uint32_t*)(aTl + rowbase + (size_t)8 * C_DIM + d) = packb(l0, l1);
    }
}

// ---------------------------------------------------------------------------
// GroupNorm (proven)
// ---------------------------------------------------------------------------
__global__ __launch_bounds__(256) void gn_kernel(
    const float* __restrict__ z, const float* __restrict__ gamma,
    const float* __restrict__ beta, float* __restrict__ outp)
{
    const int bg = blockIdx.x;
    const int b = bg >> 5, g = bg & 31;
    const float* zp = z + ((size_t)b * C_DIM + g * 16) * L_DIM;
    float* op = outp + ((size_t)b * C_DIM + g * 16) * L_DIM;
    const int t = threadIdx.x;

    float s = 0.f, ss = 0.f;
    const float4* z4 = (const float4*)zp;
    for (int i = t; i < 8192; i += 256) {
        float4 v = z4[i];
        s  += v.x + v.y + v.z + v.w;
        ss += v.x * v.x + v.y * v.y + v.z * v.z + v.w * v.w;
    }
    __shared__ float rs[8], rss[8];
    __shared__ float smu, srstd;
    #pragma unroll
    for (int o = 16; o; o >>= 1) {
        s  += __shfl_xor_sync(0xffffffffu, s, o);
        ss += __shfl_xor_sync(0xffffffffu, ss, o);
    }
    if ((t & 31) == 0) { rs[t >> 5] = s; rss[t >> 5] = ss; }
    __syncthreads();
    if (t == 0) {
        float ts = 0.f, tss = 0.f;
        #pragma unroll
        for (int wv = 0; wv < 8; wv++) { ts += rs[wv]; tss += rss[wv]; }
        float mu = ts * (1.f / 32768.f);
        float var = tss * (1.f / 32768.f) - mu * mu;
        smu = mu;
        srstd = rsqrtf(var + 1e-5f);
    }
    __syncthreads();
    const float mu = smu, rstd = srstd;
    float4* o4 = (float4*)op;
    for (int i = t; i < 8192; i += 256) {
        int ch = g * 16 + (i >> 9);
        float ga = gamma[ch] * rstd;
        float be = beta[ch];
        float4 v = z4[i];
        v.x = (v.x - mu) * ga + be;
        v.y = (v.y - mu) * ga + be;
        v.z = (v.z - mu) * ga + be;
        v.w = (v.w - mu) * ga + be;
        o4[i] = v;
    }
}

// ---------------------------------------------------------------------------
extern "C" void kernel_launch(void* const* d_in, const int* in_sizes, int n_in,
                              void* d_out, int out_size)
{
    const float* x     = (const float*)d_in[0];
    const float* Wqkv  = (const float*)d_in[1];
    const float* bqkv  = (const float*)d_in[2];
    const float* Wproj = (const float*)d_in[3];
    const float* bproj = (const float*)d_in[4];
    const float* gamma = (const float*)d_in[5];
    const float* beta  = (const float*)d_in[6];
    float* out = (float*)d_out;

    float* zbuf;
    __nv_bfloat16 *qkvh, *qkvl, *xTh, *xTl, *aTh, *aTl, *wqh, *wql, *wph, *wpl;
    cudaGetSymbolAddress((void**)&zbuf, g_z);
    cudaGetSymbolAddress((void**)&qkvh, g_qkvh);
    cudaGetSymbolAddress((void**)&qkvl, g_qkvl);
    cudaGetSymbolAddress((void**)&xTh,  g_xTh);
    cudaGetSymbolAddress((void**)&xTl,  g_xTl);
    cudaGetSymbolAddress((void**)&aTh,  g_aTh);
    cudaGetSymbolAddress((void**)&aTl,  g_aTl);
    cudaGetSymbolAddress((void**)&wqh,  g_wqh);
    cudaGetSymbolAddress((void**)&wql,  g_wql);
    cudaGetSymbolAddress((void**)&wph,  g_wph);
    cudaGetSymbolAddress((void**)&wpl,  g_wpl);

    cudaFuncSetAttribute(attn_mma_kernel, cudaFuncAttributeMaxDynamicSharedMemorySize, ATTN_SMEM);
    cudaFuncSetAttribute(mma_gemm_kernel<true, false, true>,  cudaFuncAttributeMaxDynamicSharedMemorySize, GEMM_SMEM);
    cudaFuncSetAttribute(mma_gemm_kernel<false, true, false>, cudaFuncAttributeMaxDynamicSharedMemorySize, GEMM_SMEM);

    // pre-split inputs
    tsplit_x_kernel<<<dim3(16, 8, BATCH), 256>>>(x, xTh, xTl);
    esplit_kernel<<<(3 * C_DIM * C_DIM / 4 + 255) / 256, 256>>>(Wqkv, wqh, wql, 3 * C_DIM * C_DIM / 4);
    esplit_kernel<<<(C_DIM * C_DIM / 4 + 255) / 256, 256>>>(Wproj, wph, wpl, C_DIM * C_DIM / 4);

    // qkv = clip(Wqkv @ x + bqkv) -> bf16 hi/lo [b][3C][L]
    mma_gemm_kernel<true, false, true><<<dim3(8, 12, BATCH), 512, GEMM_SMEM>>>(
        wqh, wql, xTh, xTl, nullptr, qkvh, qkvl, bqkv, nullptr,
        L_DIM, C_DIM, (size_t)CL, (size_t)3 * CL, 0);

    // attention -> att^T hi/lo bf16
    attn_mma_kernel<<<dim3(16, HEADS, BATCH), 256, ATTN_SMEM>>>(qkvh, qkvl, aTh, aTl);

    // z = Wproj @ att + bproj + x
    mma_gemm_kernel<false, true, false><<<dim3(8, 4, BATCH), 512, GEMM_SMEM>>>(
        wph, wpl, aTh, aTl, zbuf, nullptr, nullptr, bproj, x,
        L_DIM, C_DIM, (size_t)CL, (size_t)CL, (size_t)CL);

    // out = groupnorm(z)
    gn_kernel<<<dim3(BATCH * 32), 256>>>(zbuf, gamma, beta, out);
}

// round 17
// speedup vs baseline: 1.2056x; 1.0594x over previous
#include <cuda_runtime.h>
#include <cuda_bf16.h>
#include <cstdint>

#define C_DIM 512
#define L_DIM 2048
#define BATCH 4
#define HEADS 8
#define HDIM 64
#define CL (C_DIM * L_DIM)

// ---------------------------------------------------------------------------
// Helpers
// ---------------------------------------------------------------------------
__device__ __forceinline__ uint32_t s2u(const void* p) {
    uint32_t a;
    asm("{ .reg .u64 t; cvta.to.shared.u64 t, %1; cvt.u32.u64 %0, t; }" : "=r"(a) : "l"(p));
    return a;
}
__device__ __forceinline__ void ldsm4(uint32_t* r, uint32_t a) {
    asm volatile("ldmatrix.sync.aligned.m8n8.x4.shared.b16 {%0,%1,%2,%3}, [%4];"
                 : "=r"(r[0]), "=r"(r[1]), "=r"(r[2]), "=r"(r[3]) : "r"(a));
}
__device__ __forceinline__ void ldsm4t(uint32_t* r, uint32_t a) {
    asm volatile("ldmatrix.sync.aligned.m8n8.x4.trans.shared.b16 {%0,%1,%2,%3}, [%4];"
                 : "=r"(r[0]), "=r"(r[1]), "=r"(r[2]), "=r"(r[3]) : "r"(a));
}
__device__ __forceinline__ void mma16816(float* c, const uint32_t* a, const uint32_t* b) {
    asm volatile("mma.sync.aligned.m16n8k16.row.col.f32.bf16.bf16.f32 "
                 "{%0,%1,%2,%3}, {%4,%5,%6,%7}, {%8,%9}, {%0,%1,%2,%3};"
                 : "+f"(c[0]), "+f"(c[1]), "+f"(c[2]), "+f"(c[3])
                 : "r"(a[0]), "r"(a[1]), "r"(a[2]), "r"(a[3]), "r"(b[0]), "r"(b[1]));
}
#define CP16(dst, src)  asm volatile("cp.async.cg.shared.global [%0], [%1], 16;" :: "r"(dst), "l"(src))
#define CPCOMMIT()      asm volatile("cp.async.commit_group;")
#define CPWAIT1()       asm volatile("cp.async.wait_group 1;" ::: "memory")
#define CPWAIT0()       asm volatile("cp.async.wait_group 0;" ::: "memory")
#define SW(x)  ((x) ^ (((x) >> 3) & 0x70))
#define GSW(x) ((x) ^ (((x) >> 3) & 0x30))
__device__ __forceinline__ void split_bf(float x, __nv_bfloat16& h, __nv_bfloat16& l) {
    h = __float2bfloat16(x);
    l = __float2bfloat16(x - __bfloat162float(h));
}
__device__ __forceinline__ uint32_t packb(__nv_bfloat16 a, __nv_bfloat16 b) {
    __nv_bfloat162 t(a, b);
    return *(uint32_t*)&t;
}
// exp2 via FFMA/ALU only (no MUFU). |y| <= 14.5 guaranteed by clip.
__device__ __forceinline__ float exp2_poly(float y) {
    float r = y + 12582912.f;
    int n = __float_as_int(r) - 0x4B400000;
    float f = y - (r - 12582912.f);
    float p = 0.0013333558f;
    p = p * f + 0.0096181291f;
    p = p * f + 0.0555041087f;
    p = p * f + 0.2402265069f;
    p = p * f + 0.6931471825f;
    p = p * f + 1.0f;
    return __int_as_float(__float_as_int(p) + (n << 23));
}

// ---------------------------------------------------------------------------
// Scratch
// ---------------------------------------------------------------------------
__device__ float g_z[BATCH * CL];
__device__ __nv_bfloat16 g_qkvh[BATCH * 3 * CL], g_qkvl[BATCH * 3 * CL];  // [b][3C][L]
__device__ __nv_bfloat16 g_xTh[BATCH * CL], g_xTl[BATCH * CL];            // x^T [b][l][c]
__device__ __nv_bfloat16 g_aTh[BATCH * CL], g_aTl[BATCH * CL];            // att^T [b][l][c]
__device__ __nv_bfloat16 g_wqh[3 * C_DIM * C_DIM], g_wql[3 * C_DIM * C_DIM];
__device__ __nv_bfloat16 g_wph[C_DIM * C_DIM], g_wpl[C_DIM * C_DIM];

// ---------------------------------------------------------------------------
// Elementwise fp32 -> bf16 hi/lo split
// ---------------------------------------------------------------------------
__global__ __launch_bounds__(256) void esplit_kernel(
    const float* __restrict__ s, __nv_bfloat16* __restrict__ dh,
    __nv_bfloat16* __restrict__ dl, int n4)
{
    int i = blockIdx.x * 256 + threadIdx.x;
    if (i >= n4) return;
    float4 v = ((const float4*)s)[i];
    __nv_bfloat16 h0, l0, h1, l1, h2, l2, h3, l3;
    split_bf(v.x, h0, l0); split_bf(v.y, h1, l1);
    split_bf(v.z, h2, l2); split_bf(v.w, h3, l3);
    uint2 wh = { packb(h0, h1), packb(h2, h3) };
    uint2 wl = { packb(l0, l1), packb(l2, l3) };
    ((uint2*)dh)[i] = wh;
    ((uint2*)dl)[i] = wl;
}

// ---------------------------------------------------------------------------
// Transpose + split x: fp32 [64r][128c of L] -> bf16 hi/lo [128 l][64 c]
// ---------------------------------------------------------------------------
__global__ __launch_bounds__(256) void tsplit_x_kernel(
    const float* __restrict__ x, __nv_bfloat16* __restrict__ dh, __nv_bfloat16* __restrict__ dl)
{
    __shared__ __nv_bfloat16 th[128 * 64], tl[128 * 64];
    const int lc = blockIdx.x, cc = blockIdx.y, b = blockIdx.z;
    const float* src = x + ((size_t)b * C_DIM + cc * 64) * L_DIM + lc * 128;
    size_t doff = ((size_t)b * L_DIM + lc * 128) * C_DIM + cc * 64;
    __nv_bfloat16* dhp = dh + doff;
    __nv_bfloat16* dlp = dl + doff;
    const int t = threadIdx.x;
    {
        int r = t >> 2, cb = (t & 3) * 32;
        const float4* s4 = (const float4*)(src + (size_t)r * L_DIM + cb);
        #pragma unroll
        for (int u = 0; u < 8; u++) {
            float4 v = s4[u];
            float vv[4] = {v.x, v.y, v.z, v.w};
            #pragma unroll
            for (int e = 0; e < 4; e++) {
                int c = cb + 4 * u + e;
                __nv_bfloat16 hb, lb; split_bf(vv[e], hb, lb);
                th[c * 64 + r] = hb;
                tl[c * 64 + r] = lb;
            }
        }
    }
    __syncthreads();
    {
        int l = t >> 1, eo = (t & 1) * 32;
        #pragma unroll
        for (int u = 0; u < 4; u++) {
            *(uint4*)(dhp + (size_t)l * C_DIM + eo + 8 * u) = *(uint4*)&th[l * 64 + eo + 8 * u];
            *(uint4*)(dlp + (size_t)l * C_DIM + eo + 8 * u) = *(uint4*)&tl[l * 64 + eo + 8 * u];
        }
    }
}

// ---------------------------------------------------------------------------
// Tensor-core GEMM: 512 threads (16 warps -> 4/SMSP), warp tile 32x64,
// CTA tile 128x256, BK=32, cp.async 3-stage. (R16, proven)
// ---------------------------------------------------------------------------
#define GSTG 49152
#define GOFF_AL 8192
#define GOFF_BH 16384
#define GOFF_BL 32768
#define GEMM_SMEM (3 * GSTG)

template<bool CLIP, bool RES, bool OUTBF>
__global__ __launch_bounds__(512) void mma_gemm_kernel(
    const __nv_bfloat16* __restrict__ Ah, const __nv_bfloat16* __restrict__ Al,
    const __nv_bfloat16* __restrict__ Bh, const __nv_bfloat16* __restrict__ Bl,
    float* __restrict__ Cmat, __nv_bfloat16* __restrict__ obh, __nv_bfloat16* __restrict__ obl,
    const float* __restrict__ bias, const float* __restrict__ res,
    int N, int K, size_t strideB, size_t strideC, size_t strideR)
{
    extern __shared__ char gsm[];
    const uint32_t sb = s2u(gsm);

    const int t = threadIdx.x;
    const int warp = t >> 5, lane = t & 31;
    const int wm = warp & 3, wn = warp >> 2;
    const int m0w = wm * 32, n0w = wn * 64;
    const int n0 = blockIdx.x * 256, m0 = blockIdx.y * 128;

    const int ar = t >> 2, aco = (t & 3) * 16;
    const int br = t >> 1, bco = (t & 1) * 32;
    const char* pAh = (const char*)(Ah + (size_t)(m0 + ar) * K) + aco;
    const char* pAl = (const char*)(Al + (size_t)(m0 + ar) * K) + aco;
    const char* pBh = (const char*)(Bh + strideB * blockIdx.z + (size_t)(n0 + br) * K) + bco;
    const char* pBl = (const char*)(Bl + strideB * blockIdx.z + (size_t)(n0 + br) * K) + bco;
    const uint32_t dA0 = GSW(ar * 64 + aco);
    const uint32_t dB0 = GSW(br * 64 + bco), dB1 = GSW(br * 64 + bco + 16);

    const int brow = (lane & 7) + ((lane >> 4) << 3);
    const int bcol = ((lane >> 3) & 1) * 16;

    const int NCH = K >> 5;

    #pragma unroll
    for (int c = 0; c < 2; c++) {
        uint32_t base = sb + c * GSTG;
        size_t go = (size_t)c * 64;
        CP16(base + dA0, pAh + go);
        CP16(base + GOFF_AL + dA0, pAl + go);
        CP16(base + GOFF_BH + dB0, pBh + go);
        CP16(base + GOFF_BH + dB1, pBh + go + 16);
        CP16(base + GOFF_BL + dB0, pBl + go);
        CP16(base + GOFF_BL + dB1, pBl + go + 16);
        CPCOMMIT();
    }

    float acc[2][8][4] = {};
    int stg = 0, nstg = 2;

    for (int c = 0; c < NCH; c++) {
        CPWAIT1();
        __syncthreads();

        if (c + 2 < NCH) {
            uint32_t base = sb + nstg * GSTG;
            size_t go = (size_t)(c + 2) * 64;
            CP16(base + dA0, pAh + go);
            CP16(base + GOFF_AL + dA0, pAl + go);
            CP16(base + GOFF_BH + dB0, pBh + go);
            CP16(base + GOFF_BH + dB1, pBh + go + 16);
            CP16(base + GOFF_BL + dB0, pBl + go);
            CP16(base + GOFF_BL + dB1, pBl + go + 16);
            CPCOMMIT();
        }
        nstg = nstg == 2 ? 0 : nstg + 1;

        const uint32_t sA = sb + stg * GSTG;
        #pragma unroll
        for (int kt = 0; kt < 2; kt++) {
            uint32_t ah[2][4], al[2][4];
            #pragma unroll
            for (int mi = 0; mi < 2; mi++) {
                uint32_t off = GSW((m0w + mi * 16 + (lane & 15)) * 64 + kt * 32 + (lane >> 4) * 16);
                ldsm4(ah[mi], sA + off);
                ldsm4(al[mi], sA + GOFF_AL + off);
            }
            #pragma unroll
            for (int nb = 0; nb < 4; nb++) {
                uint32_t bh[4], bl[4];
                uint32_t off = GSW((n0w + nb * 16 + brow) * 64 + kt * 32 + bcol);
                ldsm4(bh, sA + GOFF_BH + off);
                ldsm4(bl, sA + GOFF_BL + off);
                #pragma unroll
                for (int mi = 0; mi < 2; mi++) {
                    mma16816(acc[mi][2 * nb],     ah[mi], bh);
                    mma16816(acc[mi][2 * nb + 1], ah[mi], bh + 2);
                }
                #pragma unroll
                for (int mi = 0; mi < 2; mi++) {
                    mma16816(acc[mi][2 * nb],     ah[mi], bl);
                    mma16816(acc[mi][2 * nb + 1], ah[mi], bl + 2);
                }
                #pragma unroll
                for (int mi = 0; mi < 2; mi++) {
                    mma16816(acc[mi][2 * nb],     al[mi], bh);
                    mma16816(acc[mi][2 * nb + 1], al[mi], bh + 2);
                }
            }
        }
        stg = stg == 2 ? 0 : stg + 1;
    }

    // ---- epilogue
    float* Cp = OUTBF ? nullptr : (Cmat + strideC * blockIdx.z);
    __nv_bfloat16* oh = OUTBF ? (obh + strideC * blockIdx.z) : nullptr;
    __nv_bfloat16* ol = OUTBF ? (obl + strideC * blockIdx.z) : nullptr;
    const float* Rp = RES ? (res + strideR * blockIdx.z) : nullptr;
    #pragma unroll
    for (int mi = 0; mi < 2; mi++) {
        int r0 = m0 + m0w + mi * 16 + (lane >> 2);
        float b0 = bias[r0], b1 = bias[r0 + 8];
        #pragma unroll
        for (int nb = 0; nb < 8; nb++) {
            int col = n0 + n0w + nb * 8 + (lane & 3) * 2;
            float2 v0 = { acc[mi][nb][0] + b0, acc[mi][nb][1] + b0 };
            float2 v1 = { acc[mi][nb][2] + b1, acc[mi][nb][3] + b1 };
            if (CLIP) {
                v0.x = fminf(10.f, fmaxf(-10.f, v0.x));
                v0.y = fminf(10.f, fmaxf(-10.f, v0.y));
                v1.x = fminf(10.f, fmaxf(-10.f, v1.x));
                v1.y = fminf(10.f, fmaxf(-10.f, v1.y));
            }
            if (RES) {
                float2 r0v = *(const float2*)(Rp + (size_t)r0 * N + col);
                float2 r1v = *(const float2*)(Rp + (size_t)(r0 + 8) * N + col);
                v0.x += r0v.x; v0.y += r0v.y;
                v1.x += r1v.x; v1.y += r1v.y;
            }
            if (OUTBF) {
                __nv_bfloat16 h0, l0, h1, l1;
                split_bf(v0.x, h0, l0); split_bf(v0.y, h1, l1);
                *(uint32_t*)(oh + (size_t)r0 * N + col) = packb(h0, h1);
                *(uint32_t*)(ol + (size_t)r0 * N + col) = packb(l0, l1);
                split_bf(v1.x, h0, l0); split_bf(v1.y, h1, l1);
                *(uint32_t*)(oh + (size_t)(r0 + 8) * N + col) = packb(h0, h1);
                *(uint32_t*)(ol + (size_t)(r0 + 8) * N + col) = packb(l0, l1);
            } else {
                *(float2*)(Cp + (size_t)r0 * N + col) = v0;
                *(float2*)(Cp + (size_t)(r0 + 8) * N + col) = v1;
            }
        }
    }
}

// ---------------------------------------------------------------------------
// Flash attention: 256 threads, 128 queries/CTA, 2 CTAs/SM (reg-capped 128),
// trans-ldsm dataflow, 3-stage cp.async KV pipeline, per-kt P packing.
// ---------------------------------------------------------------------------
#define KVSTG 32768
#define OFF_KL 8192
#define OFF_VH 16384
#define OFF_VL 24576
#define ATTN_SMEM (3 * KVSTG)

__global__ __launch_bounds__(256, 2) void attn_mma_kernel(
    const __nv_bfloat16* __restrict__ qkvh, const __nv_bfloat16* __restrict__ qkvl,
    __nv_bfloat16* __restrict__ aTh, __nv_bfloat16* __restrict__ aTl)
{
    extern __shared__ char sm[];
    const uint32_t sb = s2u(sm);
    const int tid = threadIdx.x;
    const int w = tid >> 5, lane = tid & 31;
    const int b = blockIdx.z, h = blockIdx.y;
    const int i0 = blockIdx.x * 128;

    const size_t bbase = (size_t)b * 3 * C_DIM;

    // ---- stage Q: 4 regions of 8KB: Qh(i<64), Qh(i>=64), Ql(i<64), Ql(i>=64)
    {
        const int qr = tid >> 2, qc = (tid & 3) * 16;
        #pragma unroll
        for (int half = 0; half < 2; half++) {
            const char* sqh = (const char*)(qkvh + (bbase + h * 64 + qr) * L_DIM + i0 + half * 64 + qc);
            const char* sql = (const char*)(qkvl + (bbase + h * 64 + qr) * L_DIM + i0 + half * 64 + qc);
            uint32_t d0 = SW(qr * 128 + qc * 2), d1 = SW(qr * 128 + qc * 2 + 16);
            CP16(sb + half * 8192 + d0, sqh);
            CP16(sb + half * 8192 + d1, sqh + 16);
            CP16(sb + 16384 + half * 8192 + d0, sql);
            CP16(sb + 16384 + half * 8192 + d1, sql + 16);
        }
        CPCOMMIT();
    }
    CPWAIT0();
    __syncthreads();

    // ---- Q a-fragments via trans-ldsm
    uint32_t qh[4][4], ql[4][4];
    {
        const uint32_t hofs = (w >> 2) * 8192;
        const int rd = ((lane >> 4) << 3) + (lane & 7);
        const int ci = ((w & 3) << 4) + (((lane >> 3) & 1) << 3);
        #pragma unroll
        for (int dt = 0; dt < 4; dt++) {
            uint32_t off = SW((dt * 16 + rd) * 128 + ci * 2);
            ldsm4t(qh[dt], sb + hofs + off);
            ldsm4t(ql[dt], sb + 16384 + hofs + off);
        }
    }
    __syncthreads();

    // ---- KV loader mapping
    const int kr = tid >> 2, kc = (tid & 3) * 16;
    const char* pKh = (const char*)(qkvh + (bbase + C_DIM + h * 64 + kr) * L_DIM + kc);
    const char* pKl = (const char*)(qkvl + (bbase + C_DIM + h * 64 + kr) * L_DIM + kc);
    const char* pVh = (const char*)(qkvh + (bbase + 2 * C_DIM + h * 64 + kr) * L_DIM + kc);
    const char* pVl = (const char*)(qkvl + (bbase + 2 * C_DIM + h * 64 + kr) * L_DIM + kc);
    const uint32_t dK0 = SW(kr * 128 + kc * 2), dK1 = SW(kr * 128 + kc * 2 + 16);

    #pragma unroll
    for (int tt = 0; tt < 2; tt++) {
        uint32_t base = sb + tt * KVSTG;
        size_t go = (size_t)tt * 128;
        CP16(base + dK0, pKh + go); CP16(base + dK1, pKh + go + 16);
        CP16(base + OFF_KL + dK0, pKl + go); CP16(base + OFF_KL + dK1, pKl + go + 16);
        CP16(base + OFF_VH + dK0, pVh + go); CP16(base + OFF_VH + dK1, pVh + go + 16);
        CP16(base + OFF_VL + dK0, pVl + go); CP16(base + OFF_VL + dK1, pVl + go + 16);
        CPCOMMIT();
    }

    const int krd = (((lane >> 3) & 1) << 3) + (lane & 7);
    const int kcj = (lane >> 4) << 3;
    const int brow = (lane & 7) + ((lane >> 4) << 3);
    const int bcol = ((lane >> 3) & 1) * 16;

    const float K1 = 0.125f * 1.44269504f;
    const float LIM = 10.0f * 1.44269504f;

    float oc[8][4] = {};
    float racc0 = 0.f, racc1 = 0.f;
    int stg = 0, nstg = 2;

    for (int t = 0; t < 32; t++) {
        CPWAIT1();
        __syncthreads();

        if (t + 2 < 32) {
            uint32_t base = sb + nstg * KVSTG;
            size_t go = (size_t)(t + 2) * 128;
            CP16(base + dK0, pKh + go); CP16(base + dK1, pKh + go + 16);
            CP16(base + OFF_KL + dK0, pKl + go); CP16(base + OFF_KL + dK1, pKl + go + 16);
            CP16(base + OFF_VH + dK0, pVh + go); CP16(base + OFF_VH + dK1, pVh + go + 16);
            CP16(base + OFF_VL + dK0, pVl + go); CP16(base + OFF_VL + dK1, pVl + go + 16);
            CPCOMMIT();
        }
        nstg = nstg == 2 ? 0 : nstg + 1;

        const uint32_t sKV = sb + stg * KVSTG;

        // ---- S = Q K^T, term-major
        float sc[8][4] = {};
        #pragma unroll
        for (int dt = 0; dt < 4; dt++) {
            uint32_t kh[4][4], kl[4][4];
            #pragma unroll
            for (int jb = 0; jb < 4; jb++) {
                uint32_t off = SW((dt * 16 + krd) * 128 + (jb * 16 + kcj) * 2);
                ldsm4t(kh[jb], sKV + off);
                ldsm4t(kl[jb], sKV + OFF_KL + off);
            }
            #pragma unroll
            for (int jb = 0; jb < 4; jb++) {
                mma16816(sc[2 * jb],     qh[dt], kh[jb]);
                mma16816(sc[2 * jb + 1], qh[dt], kh[jb] + 2);
            }
            #pragma unroll
            for (int jb = 0; jb < 4; jb++) {
                mma16816(sc[2 * jb],     qh[dt], kl[jb]);
                mma16816(sc[2 * jb + 1], qh[dt], kl[jb] + 2);
            }
            #pragma unroll
            for (int jb = 0; jb < 4; jb++) {
                mma16816(sc[2 * jb],     ql[dt], kh[jb]);
                mma16816(sc[2 * jb + 1], ql[dt], kh[jb] + 2);
            }
        }

        // ---- softmax numerator
        #pragma unroll
        for (int nt = 0; nt < 8; nt++) {
            #pragma unroll
            for (int k = 0; k < 4; k++) {
                float y = sc[nt][k] * K1;
                y = fminf(LIM, fmaxf(-LIM, y));
                float p = exp2_poly(y);
                sc[nt][k] = p;
                if (k < 2) racc0 += p; else racc1 += p;
            }
        }

        // ---- O += P V^T, term-major; P packed per-kt (lower reg pressure)
        #pragma unroll
        for (int kt = 0; kt < 4; kt++) {
            uint32_t ph[4], pl[4];
            {
                __nv_bfloat16 h0, l0, h1, l1;
                split_bf(sc[2 * kt][0], h0, l0); split_bf(sc[2 * kt][1], h1, l1);
                ph[0] = packb(h0, h1); pl[0] = packb(l0, l1);
                split_bf(sc[2 * kt][2], h0, l0); split_bf(sc[2 * kt][3], h1, l1);
                ph[1] = packb(h0, h1); pl[1] = packb(l0, l1);
                split_bf(sc[2 * kt + 1][0], h0, l0); split_bf(sc[2 * kt + 1][1], h1, l1);
                ph[2] = packb(h0, h1); pl[2] = packb(l0, l1);
                split_bf(sc[2 * kt + 1][2], h0, l0); split_bf(sc[2 * kt + 1][3], h1, l1);
                ph[3] = packb(h0, h1); pl[3] = packb(l0, l1);
            }
            uint32_t vvh[4][4], vvl[4][4];
            #pragma unroll
            for (int db = 0; db < 4; db++) {
                uint32_t off = SW((db * 16 + brow) * 128 + kt * 32 + bcol);
                ldsm4(vvh[db], sKV + OFF_VH + off);
                ldsm4(vvl[db], sKV + OFF_VL + off);
            }
            #pragma unroll
            for (int db = 0; db < 4; db++) {
                mma16816(oc[2 * db],     ph, vvh[db]);
                mma16816(oc[2 * db + 1], ph, vvh[db] + 2);
            }
            #pragma unroll
            for (int db = 0; db < 4; db++) {
                mma16816(oc[2 * db],     ph, vvl[db]);
                mma16816(oc[2 * db + 1], ph, vvl[db] + 2);
            }
            #pragma unroll
            for (int db = 0; db < 4; db++) {
                mma16816(oc[2 * db],     pl, vvh[db]);
                mma16816(oc[2 * db + 1], pl, vvh[db] + 2);
            }
        }
        stg = stg == 2 ? 0 : stg + 1;
    }

    // ---- row denominators (quad reduce)
    racc0 += __shfl_xor_sync(0xffffffffu, racc0, 1);
    racc0 += __shfl_xor_sync(0xffffffffu, racc0, 2);
    racc1 += __shfl_xor_sync(0xffffffffu, racc1, 1);
    racc1 += __shfl_xor_sync(0xffffffffu, racc1, 2);
    const float inv0 = 1.0f / racc0;
    const float inv1 = 1.0f / racc1;

    // ---- write att^T hi/lo bf16: [b][l][c], c = h*64 + d
    const int ibase = i0 + w * 16 + (lane >> 2);
    const size_t rowbase = ((size_t)b * L_DIM + ibase) * C_DIM + h * 64;
    #pragma unroll
    for (int nt = 0; nt < 8; nt++) {
        int d = nt * 8 + 2 * (lane & 3);
        float a0 = oc[nt][0] * inv0, a1 = oc[nt][1] * inv0;
        float a2 = oc[nt][2] * inv1, a3 = oc[nt][3] * inv1;
        __nv_bfloat16 h0, l0, h1, l1;
        split_bf(a0, h0, l0); split_bf(a1, h1, l1);
        *(uint32_t*)(aTh + rowbase + d) = packb(h0, h1);
        *(uint32_t*)(aTl + rowbase + d) = packb(l0, l1);
        split_bf(a2, h0, l0); split_bf(a3, h1, l1);
        *(uint32_t*)(aTh + rowbase + (size_t)8 * C_DIM + d) = packb(h0, h1);
        *(uint32_t*)(aTl + rowbase + (size_t)8 * C_DIM + d) = packb(l0, l1);
    }
}

// ---------------------------------------------------------------------------
// GroupNorm (proven)
// ---------------------------------------------------------------------------
__global__ __launch_bounds__(256) void gn_kernel(
    const float* __restrict__ z, const float* __restrict__ gamma,
    const float* __restrict__ beta, float* __restrict__ outp)
{
    const int bg = blockIdx.x;
    const int b = bg >> 5, g = bg & 31;
    const float* zp = z + ((size_t)b * C_DIM + g * 16) * L_DIM;
    float* op = outp + ((size_t)b * C_DIM + g * 16) * L_DIM;
    const int t = threadIdx.x;

    float s = 0.f, ss = 0.f;
    const float4* z4 = (const float4*)zp;
    for (int i = t; i < 8192; i += 256) {
        float4 v = z4[i];
        s  += v.x + v.y + v.z + v.w;
        ss += v.x * v.x + v.y * v.y + v.z * v.z + v.w * v.w;
    }
    __shared__ float rs[8], rss[8];
    __shared__ float smu, srstd;
    #pragma unroll
    for (int o = 16; o; o >>= 1) {
        s  += __shfl_xor_sync(0xffffffffu, s, o);
        ss += __shfl_xor_sync(0xffffffffu, ss, o);
    }
    if ((t & 31) == 0) { rs[t >> 5] = s; rss[t >> 5] = ss; }
    __syncthreads();
    if (t == 0) {
        float ts = 0.f, tss = 0.f;
        #pragma unroll
        for (int wv = 0; wv < 8; wv++) { ts += rs[wv]; tss += rss[wv]; }
        float mu = ts * (1.f / 32768.f);
        float var = tss * (1.f / 32768.f) - mu * mu;
        smu = mu;
        srstd = rsqrtf(var + 1e-5f);
    }
    __syncthreads();
    const float mu = smu, rstd = srstd;
    float4* o4 = (float4*)op;
    for (int i = t; i < 8192; i += 256) {
        int ch = g * 16 + (i >> 9);
        float ga = gamma[ch] * rstd;
        float be = beta[ch];
        float4 v = z4[i];
        v.x = (v.x - mu) * ga + be;
        v.y = (v.y - mu) * ga + be;
        v.z = (v.z - mu) * ga + be;
        v.w = (v.w - mu) * ga + be;
        o4[i] = v;
    }
}

// ---------------------------------------------------------------------------
extern "C" void kernel_launch(void* const* d_in, const int* in_sizes, int n_in,
                              void* d_out, int out_size)
{
    const float* x     = (const float*)d_in[0];
    const float* Wqkv  = (const float*)d_in[1];
    const float* bqkv  = (const float*)d_in[2];
    const float* Wproj = (const float*)d_in[3];
    const float* bproj = (const float*)d_in[4];
    const float* gamma = (const float*)d_in[5];
    const float* beta  = (const float*)d_in[6];
    float* out = (float*)d_out;

    float* zbuf;
    __nv_bfloat16 *qkvh, *qkvl, *xTh, *xTl, *aTh, *aTl, *wqh, *wql, *wph, *wpl;
    cudaGetSymbolAddress((void**)&zbuf, g_z);
    cudaGetSymbolAddress((void**)&qkvh, g_qkvh);
    cudaGetSymbolAddress((void**)&qkvl, g_qkvl);
    cudaGetSymbolAddress((void**)&xTh,  g_xTh);
    cudaGetSymbolAddress((void**)&xTl,  g_xTl);
    cudaGetSymbolAddress((void**)&aTh,  g_aTh);
    cudaGetSymbolAddress((void**)&aTl,  g_aTl);
    cudaGetSymbolAddress((void**)&wqh,  g_wqh);
    cudaGetSymbolAddress((void**)&wql,  g_wql);
    cudaGetSymbolAddress((void**)&wph,  g_wph);
    cudaGetSymbolAddress((void**)&wpl,  g_wpl);

    cudaFuncSetAttribute(attn_mma_kernel, cudaFuncAttributeMaxDynamicSharedMemorySize, ATTN_SMEM);
    cudaFuncSetAttribute(mma_gemm_kernel<true, false, true>,  cudaFuncAttributeMaxDynamicSharedMemorySize, GEMM_SMEM);
    cudaFuncSetAttribute(mma_gemm_kernel<false, true, false>, cudaFuncAttributeMaxDynamicSharedMemorySize, GEMM_SMEM);

    // pre-split inputs
    tsplit_x_kernel<<<dim3(16, 8, BATCH), 256>>>(x, xTh, xTl);
    esplit_kernel<<<(3 * C_DIM * C_DIM / 4 + 255) / 256, 256>>>(Wqkv, wqh, wql, 3 * C_DIM * C_DIM / 4);
    esplit_kernel<<<(C_DIM * C_DIM / 4 + 255) / 256, 256>>>(Wproj, wph, wpl, C_DIM * C_DIM / 4);

    // qkv = clip(Wqkv @ x + bqkv) -> bf16 hi/lo [b][3C][L]
    mma_gemm_kernel<true, false, true><<<dim3(8, 12, BATCH), 512, GEMM_SMEM>>>(
        wqh, wql, xTh, xTl, nullptr, qkvh, qkvl, bqkv, nullptr,
        L_DIM, C_DIM, (size_t)CL, (size_t)3 * CL, 0);

    // attention -> att^T hi/lo bf16
    attn_mma_kernel<<<dim3(16, HEADS, BATCH), 256, ATTN_SMEM>>>(qkvh, qkvl, aTh, aTl);

    // z = Wproj @ att + bproj + x
    mma_gemm_kernel<false, true, false><<<dim3(8, 4, BATCH), 512, GEMM_SMEM>>>(
        wph, wpl, aTh, aTl, zbuf, nullptr, nullptr, bproj, x,
        L_DIM, C_DIM, (size_t)CL, (size_t)CL, (size_t)CL);

    // out = groupnorm(z)
    gn_kernel<<<dim3(BATCH * 32), 256>>>(zbuf, gamma, beta, out);
}